// round 1
// baseline (speedup 1.0000x reference)
#include <cuda_runtime.h>
#include <cstdint>

#define N_NODES 50000
#define E_EDGES 800000
#define CH 128
#define HEADS 2

// ---------------- device scratch (no cudaMalloc allowed) ----------------
__device__ int   g_is64;
__device__ int   g_src[E_EDGES];
__device__ int   g_dst[E_EDGES];
__device__ float g_Q[(size_t)N_NODES * CH];
__device__ float g_K[(size_t)N_NODES * CH];
__device__ float g_V[(size_t)N_NODES * CH];
__device__ float g_e[(size_t)E_EDGES * CH];          // 409.6 MB
__device__ float g_p[(size_t)E_EDGES * HEADS];       // alpha, then p=exp(alpha-m)
__device__ int   g_m[(size_t)N_NODES * HEADS];       // ordered-int encoded segment max
__device__ float g_den[(size_t)N_NODES * HEADS];

// ---------------- dtype detection for edge_index ----------------
// If int64 (little-endian, values < 2^31), every odd 32-bit word is 0.
// If int32, odd words are random node ids (prob of all-zero ~ 0).
__global__ void detect_kernel(const int* __restrict__ w) {
    __shared__ int any_nz;
    if (threadIdx.x == 0) any_nz = 0;
    __syncthreads();
    int v = 0;
    for (int i = threadIdx.x; i < 2048; i += blockDim.x) v |= w[2 * i + 1];
    if (v) atomicOr(&any_nz, 1);
    __syncthreads();
    if (threadIdx.x == 0) g_is64 = any_nz ? 0 : 1;
}

__global__ void convert_kernel(const int* __restrict__ w) {
    int e = blockIdx.x * blockDim.x + threadIdx.x;
    if (e >= E_EDGES) return;
    if (g_is64) {
        g_src[e] = w[2 * e];
        g_dst[e] = w[2 * (E_EDGES + e)];
    } else {
        g_src[e] = w[e];
        g_dst[e] = w[E_EDGES + e];
    }
}

__global__ void init_kernel() {
    int i = blockIdx.x * blockDim.x + threadIdx.x;
    if (i < N_NODES * HEADS) {
        g_m[i]   = (int)0x80000000;  // below any ordered-float encoding
        g_den[i] = 0.0f;
    }
}

// ---------------- node GEMM: [N,128] @ [128,128] + bias, x4 ----------------
// blockIdx.y selects (Wq->g_Q, Wk->g_K, Wv->g_V, Ws->d_out)
__global__ __launch_bounds__(256) void node_gemm_kernel(
    const float* __restrict__ x,
    const float* __restrict__ Wq, const float* __restrict__ bq,
    const float* __restrict__ Wk, const float* __restrict__ bk,
    const float* __restrict__ Wv, const float* __restrict__ bv,
    const float* __restrict__ Ws, const float* __restrict__ bs,
    float* __restrict__ out)
{
    __shared__ float As[32][132];
    __shared__ float Bs[32][128];
    __shared__ float bias_s[128];

    const float* W; const float* b; float* dstp;
    switch (blockIdx.y) {
        case 0: W = Wq; b = bq; dstp = g_Q; break;
        case 1: W = Wk; b = bk; dstp = g_K; break;
        case 2: W = Wv; b = bv; dstp = g_V; break;
        default: W = Ws; b = bs; dstp = out; break;
    }

    int tid = threadIdx.x;
    int m0 = blockIdx.x * 128;
    if (tid < 128) bias_s[tid] = b[tid];

    int tn = tid & 15, tm = tid >> 4;
    float acc[2][2][4][4];
#pragma unroll
    for (int a = 0; a < 2; a++)
#pragma unroll
        for (int c = 0; c < 2; c++)
#pragma unroll
            for (int i = 0; i < 4; i++)
#pragma unroll
                for (int j = 0; j < 4; j++) acc[a][c][i][j] = 0.0f;

    for (int kc = 0; kc < 4; kc++) {
        __syncthreads();
        // A tile: x[m0+m][kc*32+c] transposed into As[c][m]
#pragma unroll
        for (int r = 0; r < 4; r++) {
            int idx = tid + 256 * r;
            int m = idx >> 3, c4 = idx & 7;
            int row = m0 + m;
            float4 v = make_float4(0, 0, 0, 0);
            if (row < N_NODES)
                v = *(const float4*)&x[(size_t)row * 128 + kc * 32 + c4 * 4];
            As[c4 * 4 + 0][m] = v.x;
            As[c4 * 4 + 1][m] = v.y;
            As[c4 * 4 + 2][m] = v.z;
            As[c4 * 4 + 3][m] = v.w;
        }
        // B tile
#pragma unroll
        for (int r = 0; r < 4; r++) {
            int idx = tid + 256 * r;
            int row = idx >> 5, c4 = idx & 31;
            *(float4*)&Bs[row][c4 * 4] =
                *(const float4*)&W[(size_t)(kc * 32 + row) * 128 + c4 * 4];
        }
        __syncthreads();
#pragma unroll
        for (int k = 0; k < 32; k++) {
            float a0[4], a1[4], b0[4], b1[4];
            *(float4*)a0 = *(const float4*)&As[k][tm * 4];
            *(float4*)a1 = *(const float4*)&As[k][64 + tm * 4];
            *(float4*)b0 = *(const float4*)&Bs[k][tn * 4];
            *(float4*)b1 = *(const float4*)&Bs[k][64 + tn * 4];
#pragma unroll
            for (int i = 0; i < 4; i++)
#pragma unroll
                for (int j = 0; j < 4; j++) {
                    acc[0][0][i][j] += a0[i] * b0[j];
                    acc[0][1][i][j] += a0[i] * b1[j];
                    acc[1][0][i][j] += a1[i] * b0[j];
                    acc[1][1][i][j] += a1[i] * b1[j];
                }
        }
    }
    // store with bias
#pragma unroll
    for (int ri = 0; ri < 2; ri++)
#pragma unroll
        for (int i = 0; i < 4; i++) {
            int row = m0 + ri * 64 + tm * 4 + i;
            if (row >= N_NODES) continue;
#pragma unroll
            for (int ci = 0; ci < 2; ci++) {
                int col = ci * 64 + tn * 4;
                float4 o;
                o.x = acc[ri][ci][i][0] + bias_s[col + 0];
                o.y = acc[ri][ci][i][1] + bias_s[col + 1];
                o.z = acc[ri][ci][i][2] + bias_s[col + 2];
                o.w = acc[ri][ci][i][3] + bias_s[col + 3];
                *(float4*)&dstp[(size_t)row * 128 + col] = o;
            }
        }
}

// ---------------- fused edge GEMM + alpha + segment-max ----------------
// e = [cos(rel_t*Wt+bt) | msg] @ We   (K=256, 128-edge tile)
__global__ __launch_bounds__(256) void edge_gemm_kernel(
    const float* __restrict__ msg, const float* __restrict__ t,
    const float* __restrict__ last_update,
    const float* __restrict__ Wtime, const float* __restrict__ btime,
    const float* __restrict__ We)
{
    __shared__ float As[32][132];
    __shared__ float Bs[32][128];
    __shared__ float rel_s[128];
    __shared__ float Wt_s[128], bt_s[128];
    __shared__ int   srcs[128], dsts[128];

    int tid = threadIdx.x;
    int e0 = blockIdx.x * 128;

    if (tid < 128) {
        int s = g_src[e0 + tid];
        int d = g_dst[e0 + tid];
        srcs[tid] = s;
        dsts[tid] = d;
        rel_s[tid] = last_update[s] - t[e0 + tid];
        Wt_s[tid] = Wtime[tid];
        bt_s[tid] = btime[tid];
    }

    int tn = tid & 15, tm = tid >> 4;
    float acc[2][2][4][4];
#pragma unroll
    for (int a = 0; a < 2; a++)
#pragma unroll
        for (int c = 0; c < 2; c++)
#pragma unroll
            for (int i = 0; i < 4; i++)
#pragma unroll
                for (int j = 0; j < 4; j++) acc[a][c][i][j] = 0.0f;

    for (int kc = 0; kc < 8; kc++) {
        __syncthreads();
        if (kc < 4) {
            // time-encoding part of A, generated on the fly
#pragma unroll
            for (int r = 0; r < 16; r++) {
                int idx = tid + 256 * r;
                int m = idx >> 5, kk = idx & 31;
                As[kk][m] = __cosf(rel_s[m] * Wt_s[kc * 32 + kk] + bt_s[kc * 32 + kk]);
            }
        } else {
            // msg part of A
#pragma unroll
            for (int r = 0; r < 4; r++) {
                int idx = tid + 256 * r;
                int m = idx >> 3, c4 = idx & 7;
                float4 v = *(const float4*)&msg[(size_t)(e0 + m) * 128 + (kc - 4) * 32 + c4 * 4];
                As[c4 * 4 + 0][m] = v.x;
                As[c4 * 4 + 1][m] = v.y;
                As[c4 * 4 + 2][m] = v.z;
                As[c4 * 4 + 3][m] = v.w;
            }
        }
#pragma unroll
        for (int r = 0; r < 4; r++) {
            int idx = tid + 256 * r;
            int row = idx >> 5, c4 = idx & 31;
            *(float4*)&Bs[row][c4 * 4] =
                *(const float4*)&We[(size_t)(kc * 32 + row) * 128 + c4 * 4];
        }
        __syncthreads();
#pragma unroll
        for (int k = 0; k < 32; k++) {
            float a0[4], a1[4], b0[4], b1[4];
            *(float4*)a0 = *(const float4*)&As[k][tm * 4];
            *(float4*)a1 = *(const float4*)&As[k][64 + tm * 4];
            *(float4*)b0 = *(const float4*)&Bs[k][tn * 4];
            *(float4*)b1 = *(const float4*)&Bs[k][64 + tn * 4];
#pragma unroll
            for (int i = 0; i < 4; i++)
#pragma unroll
                for (int j = 0; j < 4; j++) {
                    acc[0][0][i][j] += a0[i] * b0[j];
                    acc[0][1][i][j] += a0[i] * b1[j];
                    acc[1][0][i][j] += a1[i] * b0[j];
                    acc[1][1][i][j] += a1[i] * b1[j];
                }
        }
    }

    // store e tile to global (semi-coalesced float4 stores)
#pragma unroll
    for (int ri = 0; ri < 2; ri++)
#pragma unroll
        for (int i = 0; i < 4; i++) {
            int m = ri * 64 + tm * 4 + i;
            size_t base = (size_t)(e0 + m) * 128;
#pragma unroll
            for (int ci = 0; ci < 2; ci++) {
                float4 o;
                o.x = acc[ri][ci][i][0];
                o.y = acc[ri][ci][i][1];
                o.z = acc[ri][ci][i][2];
                o.w = acc[ri][ci][i][3];
                *(float4*)&g_e[base + ci * 64 + tn * 4] = o;
            }
        }
    __syncthreads();  // global writes by block visible to block

    // alpha phase: thread -> (edge m, head h)
    int m = tid >> 1, h = tid & 1;
    int dnode = dsts[m], snode = srcs[m];
    const float4* qrow = (const float4*)&g_Q[(size_t)dnode * 128 + h * 64];
    const float4* krow = (const float4*)&g_K[(size_t)snode * 128 + h * 64];
    const float4* erow = (const float4*)&g_e[(size_t)(e0 + m) * 128 + h * 64];
    float s = 0.0f;
#pragma unroll
    for (int c = 0; c < 16; c++) {
        float4 q = qrow[c], k = krow[c], ev = erow[c];
        s += q.x * (k.x + ev.x) + q.y * (k.y + ev.y) +
             q.z * (k.z + ev.z) + q.w * (k.w + ev.w);
    }
    s *= 0.125f;  // 1/sqrt(64)
    g_p[(size_t)(e0 + m) * 2 + h] = s;

    int enc = __float_as_int(s);
    enc = (enc < 0) ? (enc ^ 0x7fffffff) : enc;
    atomicMax(&g_m[dnode * 2 + h], enc);
}

// ---------------- exp + segment denom ----------------
__global__ void exp_kernel() {
    int i = blockIdx.x * blockDim.x + threadIdx.x;
    if (i >= E_EDGES * HEADS) return;
    int e = i >> 1, h = i & 1;
    int d = g_dst[e];
    int enc = g_m[d * 2 + h];
    enc = (enc < 0) ? (enc ^ 0x7fffffff) : enc;
    float mval = __int_as_float(enc);
    float p = __expf(g_p[i] - mval);
    g_p[i] = p;
    atomicAdd(&g_den[d * 2 + h], p);
}

// ---------------- scatter: out[dst] += attn * (v[src] + e) ----------------
__global__ __launch_bounds__(256) void scatter_kernel(float* __restrict__ out) {
    int warp = (blockIdx.x * blockDim.x + threadIdx.x) >> 5;
    int lane = threadIdx.x & 31;
    if (warp >= E_EDGES) return;
    int e = warp;
    int s = g_src[e], d = g_dst[e];
    int h = lane >> 4;  // lanes 0-15 -> head 0 (cols 0..63), 16-31 -> head 1
    float attn = g_p[(size_t)e * 2 + h] / g_den[d * 2 + h];
    float4 v  = *(const float4*)&g_V[(size_t)s * 128 + lane * 4];
    float4 ev = *(const float4*)&g_e[(size_t)e * 128 + lane * 4];
    float4 o = make_float4(attn * (v.x + ev.x), attn * (v.y + ev.y),
                           attn * (v.z + ev.z), attn * (v.w + ev.w));
    atomicAdd((float4*)&out[(size_t)d * 128 + lane * 4], o);
}

// ---------------- launcher ----------------
extern "C" void kernel_launch(void* const* d_in, const int* in_sizes, int n_in,
                              void* d_out, int out_size) {
    const float* x      = (const float*)d_in[0];
    const float* lu     = (const float*)d_in[1];
    const float* t      = (const float*)d_in[2];
    const float* msg    = (const float*)d_in[3];
    const int*   eiw    = (const int*)d_in[4];   // int64 or int32, detected on device
    const float* Wt     = (const float*)d_in[5];
    const float* bt     = (const float*)d_in[6];
    const float* Wq     = (const float*)d_in[7];
    const float* bq     = (const float*)d_in[8];
    const float* Wk     = (const float*)d_in[9];
    const float* bk     = (const float*)d_in[10];
    const float* Wv     = (const float*)d_in[11];
    const float* bv     = (const float*)d_in[12];
    const float* We     = (const float*)d_in[13];
    const float* Ws     = (const float*)d_in[14];
    const float* bs     = (const float*)d_in[15];
    float* out = (float*)d_out;

    detect_kernel<<<1, 256>>>(eiw);
    convert_kernel<<<(E_EDGES + 255) / 256, 256>>>(eiw);
    init_kernel<<<(N_NODES * HEADS + 255) / 256, 256>>>();
    node_gemm_kernel<<<dim3((N_NODES + 127) / 128, 4), 256>>>(
        x, Wq, bq, Wk, bk, Wv, bv, Ws, bs, out);
    edge_gemm_kernel<<<E_EDGES / 128, 256>>>(msg, t, lu, Wt, bt, We);
    exp_kernel<<<(E_EDGES * HEADS + 255) / 256, 256>>>();
    scatter_kernel<<<E_EDGES / 8, 256>>>(out);
}

// round 3
// speedup vs baseline: 1.5540x; 1.5540x over previous
#include <cuda_runtime.h>
#include <cstdint>

#define N_NODES 50000
#define E_EDGES 800000

// ---------------- device scratch ----------------
__device__ int   g_is64;
__device__ int   g_src[E_EDGES];
__device__ int   g_dst[E_EDGES];
__device__ float g_Q[(size_t)N_NODES * 128];
__device__ float g_K[(size_t)N_NODES * 128];
__device__ float g_V[(size_t)N_NODES * 128];
__device__ float g_e[(size_t)E_EDGES * 128];     // stores v[src] + e
__device__ float g_p[(size_t)E_EDGES * 2];
__device__ int   g_m[(size_t)N_NODES * 2];
__device__ float g_den[(size_t)N_NODES * 2];

// ---------------- helpers ----------------
__device__ __forceinline__ uint32_t to_tf32(float f) {
    uint32_t r;
    asm("cvt.rna.tf32.f32 %0, %1;" : "=r"(r) : "f"(f));
    return r;
}
__device__ __forceinline__ void mma_tf32(float* c, const uint32_t* a, const uint32_t* b) {
    asm volatile(
        "mma.sync.aligned.m16n8k8.row.col.f32.tf32.tf32.f32 "
        "{%0,%1,%2,%3}, {%4,%5,%6,%7}, {%8,%9}, {%0,%1,%2,%3};"
        : "+f"(c[0]), "+f"(c[1]), "+f"(c[2]), "+f"(c[3])
        : "r"(a[0]), "r"(a[1]), "r"(a[2]), "r"(a[3]), "r"(b[0]), "r"(b[1]));
}

// ---------------- edge index handling ----------------
__global__ void detect_kernel(const int* __restrict__ w) {
    __shared__ int any_nz;
    if (threadIdx.x == 0) any_nz = 0;
    __syncthreads();
    int v = 0;
    for (int i = threadIdx.x; i < 2048; i += blockDim.x) v |= w[2 * i + 1];
    if (v) atomicOr(&any_nz, 1);
    __syncthreads();
    if (threadIdx.x == 0) g_is64 = any_nz ? 0 : 1;
}

__global__ void convert_kernel(const int* __restrict__ w) {
    int e = blockIdx.x * blockDim.x + threadIdx.x;
    if (e >= E_EDGES) return;
    if (g_is64) { g_src[e] = w[2 * e]; g_dst[e] = w[2 * (E_EDGES + e)]; }
    else        { g_src[e] = w[e];     g_dst[e] = w[E_EDGES + e]; }
}

__global__ void init_kernel() {
    int i = blockIdx.x * blockDim.x + threadIdx.x;
    if (i < N_NODES * 2) { g_m[i] = (int)0x80000000; g_den[i] = 0.0f; }
}

// ---------------- node GEMM (validated in R1) ----------------
__global__ __launch_bounds__(256) void node_gemm_kernel(
    const float* __restrict__ x,
    const float* __restrict__ Wq, const float* __restrict__ bq,
    const float* __restrict__ Wk, const float* __restrict__ bk,
    const float* __restrict__ Wv, const float* __restrict__ bv,
    const float* __restrict__ Ws, const float* __restrict__ bs,
    float* __restrict__ out)
{
    __shared__ float As[32][132];
    __shared__ float Bs[32][128];
    __shared__ float bias_s[128];

    const float* W; const float* b; float* dstp;
    switch (blockIdx.y) {
        case 0: W = Wq; b = bq; dstp = g_Q; break;
        case 1: W = Wk; b = bk; dstp = g_K; break;
        case 2: W = Wv; b = bv; dstp = g_V; break;
        default: W = Ws; b = bs; dstp = out; break;
    }

    int tid = threadIdx.x;
    int m0 = blockIdx.x * 128;
    if (tid < 128) bias_s[tid] = b[tid];

    int tn = tid & 15, tm = tid >> 4;
    float acc[2][2][4][4];
#pragma unroll
    for (int a = 0; a < 2; a++)
#pragma unroll
        for (int c = 0; c < 2; c++)
#pragma unroll
            for (int i = 0; i < 4; i++)
#pragma unroll
                for (int j = 0; j < 4; j++) acc[a][c][i][j] = 0.0f;

    for (int kc = 0; kc < 4; kc++) {
        __syncthreads();
#pragma unroll
        for (int r = 0; r < 4; r++) {
            int idx = tid + 256 * r;
            int m = idx >> 3, c4 = idx & 7;
            int row = m0 + m;
            float4 v = make_float4(0, 0, 0, 0);
            if (row < N_NODES)
                v = *(const float4*)&x[(size_t)row * 128 + kc * 32 + c4 * 4];
            As[c4 * 4 + 0][m] = v.x;
            As[c4 * 4 + 1][m] = v.y;
            As[c4 * 4 + 2][m] = v.z;
            As[c4 * 4 + 3][m] = v.w;
        }
#pragma unroll
        for (int r = 0; r < 4; r++) {
            int idx = tid + 256 * r;
            int row = idx >> 5, c4 = idx & 31;
            *(float4*)&Bs[row][c4 * 4] =
                *(const float4*)&W[(size_t)(kc * 32 + row) * 128 + c4 * 4];
        }
        __syncthreads();
#pragma unroll
        for (int k = 0; k < 32; k++) {
            float a0[4], a1[4], b0[4], b1[4];
            *(float4*)a0 = *(const float4*)&As[k][tm * 4];
            *(float4*)a1 = *(const float4*)&As[k][64 + tm * 4];
            *(float4*)b0 = *(const float4*)&Bs[k][tn * 4];
            *(float4*)b1 = *(const float4*)&Bs[k][64 + tn * 4];
#pragma unroll
            for (int i = 0; i < 4; i++)
#pragma unroll
                for (int j = 0; j < 4; j++) {
                    acc[0][0][i][j] += a0[i] * b0[j];
                    acc[0][1][i][j] += a0[i] * b1[j];
                    acc[1][0][i][j] += a1[i] * b0[j];
                    acc[1][1][i][j] += a1[i] * b1[j];
                }
        }
    }
#pragma unroll
    for (int ri = 0; ri < 2; ri++)
#pragma unroll
        for (int i = 0; i < 4; i++) {
            int row = m0 + ri * 64 + tm * 4 + i;
            if (row >= N_NODES) continue;
#pragma unroll
            for (int ci = 0; ci < 2; ci++) {
                int col = ci * 64 + tn * 4;
                float4 o;
                o.x = acc[ri][ci][i][0] + bias_s[col + 0];
                o.y = acc[ri][ci][i][1] + bias_s[col + 1];
                o.z = acc[ri][ci][i][2] + bias_s[col + 2];
                o.w = acc[ri][ci][i][3] + bias_s[col + 3];
                *(float4*)&dstp[(size_t)row * 128 + col] = o;
            }
        }
}

// ---------------- tf32 mma.sync edge GEMM + alpha + segment-max ----------------
// Per CTA: 128 edges x 128 cols, K=256 in 8 chunks of 32.
// A = [cos(rel_t*Wt+bt) | msg], B = We (k-major). Warp tile m32 x n64.
#define EDGE_SMEM (128 * 132 * 4)

__global__ __launch_bounds__(256, 2) void edge_mma_kernel(
    const float* __restrict__ msg, const float* __restrict__ t,
    const float* __restrict__ lu,
    const float* __restrict__ Wt, const float* __restrict__ bt,
    const float* __restrict__ We)
{
    extern __shared__ float sm[];
    float (*As)[132] = (float(*)[132])sm;              // [32][132]
    float (*Bs)[132] = (float(*)[132])(sm + 32 * 132); // [32][132]
    float (*Es)[132] = (float(*)[132])sm;              // [128][132] (aliases after k-loop)

    __shared__ float rel_s[128], Wt_s[128], bt_s[128];
    __shared__ int srcs[128], dsts[128];

    const int tid = threadIdx.x;
    const int wid = tid >> 5, lane = tid & 31;
    const int l4 = lane & 3, lg = lane >> 2;
    const int e0 = blockIdx.x * 128;
    const int m0 = (wid & 3) * 32;      // warp row origin
    const int n0 = (wid >> 2) * 64;     // warp col origin

    if (tid < 128) {
        int s = g_src[e0 + tid], d = g_dst[e0 + tid];
        srcs[tid] = s; dsts[tid] = d;
        rel_s[tid] = lu[s] - t[e0 + tid];
        Wt_s[tid] = Wt[tid];
        bt_s[tid] = bt[tid];
    }

    float acc[2][8][4];
#pragma unroll
    for (int mt = 0; mt < 2; mt++)
#pragma unroll
        for (int nt = 0; nt < 8; nt++)
#pragma unroll
            for (int j = 0; j < 4; j++) acc[mt][nt][j] = 0.0f;

    for (int c = 0; c < 8; c++) {
        __syncthreads();
        if (c < 4) {
            // time-encoding chunk: cos via even Taylor poly (|x| < 0.5, err < 2e-9)
#pragma unroll
            for (int g = 0; g < 16; g++) {
                int idx = g * 256 + tid;
                int m = idx >> 5, kk = idx & 31;
                float xx = fmaf(rel_s[m], Wt_s[c * 32 + kk], bt_s[c * 32 + kk]);
                float y = xx * xx;
                float p = fmaf(y, -2.7557319224e-7f, 2.4801587302e-5f);
                p = fmaf(y, p, -1.3888888889e-3f);
                p = fmaf(y, p, 4.1666666667e-2f);
                p = fmaf(y, p, -0.5f);
                As[kk][m] = fmaf(y, p, 1.0f);
            }
        } else {
#pragma unroll
            for (int g = 0; g < 4; g++) {
                int idx = g * 256 + tid;
                int m = idx >> 3, c4 = idx & 7;
                float4 v = *(const float4*)&msg[(size_t)(e0 + m) * 128 + (c - 4) * 32 + c4 * 4];
                As[c4 * 4 + 0][m] = v.x;
                As[c4 * 4 + 1][m] = v.y;
                As[c4 * 4 + 2][m] = v.z;
                As[c4 * 4 + 3][m] = v.w;
            }
        }
#pragma unroll
        for (int g = 0; g < 4; g++) {
            int idx = g * 256 + tid;
            int row = idx >> 5, c4 = idx & 31;
            *(float4*)&Bs[row][c4 * 4] =
                *(const float4*)&We[(size_t)(c * 32 + row) * 128 + c4 * 4];
        }
        __syncthreads();

#pragma unroll
        for (int ks = 0; ks < 4; ks++) {
            const int k0 = ks * 8;
            uint32_t a[2][4], b[8][2];
#pragma unroll
            for (int mt = 0; mt < 2; mt++) {
                a[mt][0] = to_tf32(As[k0 + l4][m0 + mt * 16 + lg]);
                a[mt][1] = to_tf32(As[k0 + l4][m0 + mt * 16 + lg + 8]);
                a[mt][2] = to_tf32(As[k0 + l4 + 4][m0 + mt * 16 + lg]);
                a[mt][3] = to_tf32(As[k0 + l4 + 4][m0 + mt * 16 + lg + 8]);
            }
#pragma unroll
            for (int nt = 0; nt < 8; nt++) {
                b[nt][0] = to_tf32(Bs[k0 + l4][n0 + nt * 8 + lg]);
                b[nt][1] = to_tf32(Bs[k0 + l4 + 4][n0 + nt * 8 + lg]);
            }
#pragma unroll
            for (int mt = 0; mt < 2; mt++)
#pragma unroll
                for (int nt = 0; nt < 8; nt++)
                    mma_tf32(acc[mt][nt], a[mt], b[nt]);
        }
    }

    // ---- dump accumulators to SMEM epilogue tile ----
    __syncthreads();
#pragma unroll
    for (int mt = 0; mt < 2; mt++)
#pragma unroll
        for (int nt = 0; nt < 8; nt++) {
            int r = m0 + mt * 16 + lg;
            int cc = n0 + nt * 8 + 2 * l4;
            *(float2*)&Es[r][cc]     = make_float2(acc[mt][nt][0], acc[mt][nt][1]);
            *(float2*)&Es[r + 8][cc] = make_float2(acc[mt][nt][2], acc[mt][nt][3]);
        }
    __syncthreads();

    // ---- epilogue: thread -> (edge r, head h) ----
    const int r = tid >> 1, h = tid & 1;
    int snode = srcs[r], dnode = dsts[r];
    const float4* q4 = (const float4*)&g_Q[(size_t)dnode * 128 + h * 64];
    const float4* k4 = (const float4*)&g_K[(size_t)snode * 128 + h * 64];
    const float4* v4 = (const float4*)&g_V[(size_t)snode * 128 + h * 64];
    float4* o4 = (float4*)&g_e[(size_t)(e0 + r) * 128 + h * 64];
    const float* erow = &Es[r][h * 64];
    float s = 0.0f;
#pragma unroll
    for (int c = 0; c < 16; c++) {
        float4 q = q4[c], k = k4[c], v = v4[c];
        float4 ev = *(const float4*)&erow[c * 4];
        s += q.x * (k.x + ev.x) + q.y * (k.y + ev.y) +
             q.z * (k.z + ev.z) + q.w * (k.w + ev.w);
        o4[c] = make_float4(v.x + ev.x, v.y + ev.y, v.z + ev.z, v.w + ev.w);
    }
    s *= 0.125f;
    g_p[(size_t)(e0 + r) * 2 + h] = s;
    int enc = __float_as_int(s);
    enc = (enc < 0) ? (enc ^ 0x7fffffff) : enc;
    atomicMax(&g_m[dnode * 2 + h], enc);
}

// ---------------- exp + segment denom ----------------
__global__ void exp_kernel() {
    int i = blockIdx.x * blockDim.x + threadIdx.x;
    if (i >= E_EDGES * 2) return;
    int e = i >> 1, h = i & 1;
    int d = g_dst[e];
    int enc = g_m[d * 2 + h];
    enc = (enc < 0) ? (enc ^ 0x7fffffff) : enc;
    float mval = __int_as_float(enc);
    float p = __expf(g_p[i] - mval);
    g_p[i] = p;
    atomicAdd(&g_den[d * 2 + h], p);
}

// ---------------- scatter: out[dst] += attn * (v+e) ----------------
__global__ __launch_bounds__(256) void scatter_kernel(float* __restrict__ out) {
    int gw = (blockIdx.x * blockDim.x + threadIdx.x) >> 5;
    int lane = threadIdx.x & 31;
    if (gw >= E_EDGES) return;
    int d = g_dst[gw];
    int h = lane >> 4;
    float attn = g_p[(size_t)gw * 2 + h] / g_den[d * 2 + h];
    float4 ve = *(const float4*)&g_e[(size_t)gw * 128 + lane * 4];
    atomicAdd((float4*)&out[(size_t)d * 128 + lane * 4],
              make_float4(attn * ve.x, attn * ve.y, attn * ve.z, attn * ve.w));
}

// ---------------- launcher ----------------
extern "C" void kernel_launch(void* const* d_in, const int* in_sizes, int n_in,
                              void* d_out, int out_size) {
    const float* x   = (const float*)d_in[0];
    const float* lu  = (const float*)d_in[1];
    const float* t   = (const float*)d_in[2];
    const float* msg = (const float*)d_in[3];
    const int*   eiw = (const int*)d_in[4];
    const float* Wt  = (const float*)d_in[5];
    const float* bt  = (const float*)d_in[6];
    const float* Wq  = (const float*)d_in[7];
    const float* bq  = (const float*)d_in[8];
    const float* Wk  = (const float*)d_in[9];
    const float* bk  = (const float*)d_in[10];
    const float* Wv  = (const float*)d_in[11];
    const float* bv  = (const float*)d_in[12];
    const float* We  = (const float*)d_in[13];
    const float* Ws  = (const float*)d_in[14];
    const float* bs  = (const float*)d_in[15];
    float* out = (float*)d_out;

    cudaFuncSetAttribute(edge_mma_kernel,
                         cudaFuncAttributeMaxDynamicSharedMemorySize, EDGE_SMEM);

    detect_kernel<<<1, 256>>>(eiw);
    convert_kernel<<<(E_EDGES + 255) / 256, 256>>>(eiw);
    init_kernel<<<(N_NODES * 2 + 255) / 256, 256>>>();
    node_gemm_kernel<<<dim3((N_NODES + 127) / 128, 4), 256>>>(
        x, Wq, bq, Wk, bk, Wv, bv, Ws, bs, out);
    edge_mma_kernel<<<E_EDGES / 128, 256, EDGE_SMEM>>>(msg, t, lu, Wt, bt, We);
    exp_kernel<<<(E_EDGES * 2 + 255) / 256, 256>>>();
    scatter_kernel<<<E_EDGES / 8, 256>>>(out);
}

// round 4
// speedup vs baseline: 1.9379x; 1.2470x over previous
#include <cuda_runtime.h>
#include <cstdint>

#define N_NODES 50000
#define E_EDGES 800000

// ---------------- device scratch ----------------
__device__ int   g_is64;
__device__ int   g_src[E_EDGES];
__device__ int   g_dst[E_EDGES];
__device__ float g_Q[(size_t)N_NODES * 128];
__device__ float g_K[(size_t)N_NODES * 128];
__device__ float g_V[(size_t)N_NODES * 128];
__device__ float g_e[(size_t)E_EDGES * 128];     // stores v[src] + e
__device__ float g_p[(size_t)E_EDGES * 2];
__device__ int   g_m[(size_t)N_NODES * 2];
__device__ float g_den[(size_t)N_NODES * 2];
__device__ float g_D[7 * 128];                   // time-poly coefficients

// ---------------- helpers ----------------
__device__ __forceinline__ uint32_t to_tf32(float f) {
    uint32_t r;
    asm("cvt.rna.tf32.f32 %0, %1;" : "=r"(r) : "f"(f));
    return r;
}
__device__ __forceinline__ void mma_tf32(float* c, const uint32_t* a, const uint32_t* b) {
    asm volatile(
        "mma.sync.aligned.m16n8k8.row.col.f32.tf32.tf32.f32 "
        "{%0,%1,%2,%3}, {%4,%5,%6,%7}, {%8,%9}, {%0,%1,%2,%3};"
        : "+f"(c[0]), "+f"(c[1]), "+f"(c[2]), "+f"(c[3])
        : "r"(a[0]), "r"(a[1]), "r"(a[2]), "r"(a[3]), "r"(b[0]), "r"(b[1]));
}

// ---------------- edge index handling ----------------
__global__ void detect_kernel(const int* __restrict__ w) {
    __shared__ int any_nz;
    if (threadIdx.x == 0) any_nz = 0;
    __syncthreads();
    int v = 0;
    for (int i = threadIdx.x; i < 2048; i += blockDim.x) v |= w[2 * i + 1];
    if (v) atomicOr(&any_nz, 1);
    __syncthreads();
    if (threadIdx.x == 0) g_is64 = any_nz ? 0 : 1;
}

__global__ void convert_kernel(const int* __restrict__ w) {
    int e = blockIdx.x * blockDim.x + threadIdx.x;
    if (e >= E_EDGES) return;
    if (g_is64) { g_src[e] = w[2 * e]; g_dst[e] = w[2 * (E_EDGES + e)]; }
    else        { g_src[e] = w[e];     g_dst[e] = w[E_EDGES + e]; }
}

__global__ void init_kernel() {
    int i = blockIdx.x * blockDim.x + threadIdx.x;
    if (i < N_NODES * 2) { g_m[i] = (int)0x80000000; g_den[i] = 0.0f; }
}

// ---------------- time-poly coefficient prep ----------------
// D[j][n] = sum_k (w_k^j / j!) * cos(b_k + j*pi/2) * We[k][n],  j = 0..6
__global__ void prep_D_kernel(const float* __restrict__ Wt,
                              const float* __restrict__ bt,
                              const float* __restrict__ We) {
    __shared__ float cjk[7][128];
    int tid = threadIdx.x;  // 128 threads
    {
        float w = Wt[tid], b = bt[tid];
        float cb = cosf(b), sb = sinf(b);
        float base[4] = {cb, -sb, -cb, sb};
        float wj = 1.0f;
#pragma unroll
        for (int j = 0; j < 7; j++) {
            cjk[j][tid] = wj * base[j & 3];
            wj *= w / (float)(j + 1);
        }
    }
    __syncthreads();
    float acc[7] = {0, 0, 0, 0, 0, 0, 0};
    for (int k = 0; k < 128; k++) {
        float we = We[(size_t)k * 128 + tid];
#pragma unroll
        for (int j = 0; j < 7; j++) acc[j] = fmaf(cjk[j][k], we, acc[j]);
    }
#pragma unroll
    for (int j = 0; j < 7; j++) g_D[j * 128 + tid] = acc[j];
}

// ---------------- tf32 node GEMM: [N,128] @ [128,128] + bias, x4 ----------------
#define NODE_SMEM (2 * 32 * 132 * 4)

__global__ __launch_bounds__(256, 2) void node_mma_kernel(
    const float* __restrict__ x,
    const float* __restrict__ Wq, const float* __restrict__ bq,
    const float* __restrict__ Wk, const float* __restrict__ bk,
    const float* __restrict__ Wv, const float* __restrict__ bv,
    const float* __restrict__ Ws, const float* __restrict__ bs,
    float* __restrict__ out)
{
    extern __shared__ uint32_t smu[];
    uint32_t (*As)[132] = (uint32_t(*)[132])smu;
    uint32_t (*Bs)[132] = (uint32_t(*)[132])(smu + 32 * 132);
    __shared__ float bias_s[128];

    const float* W; const float* b; float* dstp;
    switch (blockIdx.y) {
        case 0: W = Wq; b = bq; dstp = g_Q; break;
        case 1: W = Wk; b = bk; dstp = g_K; break;
        case 2: W = Wv; b = bv; dstp = g_V; break;
        default: W = Ws; b = bs; dstp = out; break;
    }

    const int tid = threadIdx.x;
    const int wid = tid >> 5, lane = tid & 31;
    const int l4 = lane & 3, lg = lane >> 2;
    const int mB = blockIdx.x * 128;
    const int m0 = (wid & 3) * 32;
    const int n0 = (wid >> 2) * 64;

    if (tid < 128) bias_s[tid] = b[tid];

    float acc[2][8][4];
#pragma unroll
    for (int mt = 0; mt < 2; mt++)
#pragma unroll
        for (int nt = 0; nt < 8; nt++)
#pragma unroll
            for (int j = 0; j < 4; j++) acc[mt][nt][j] = 0.0f;

    for (int c = 0; c < 4; c++) {
        __syncthreads();
#pragma unroll
        for (int g = 0; g < 4; g++) {
            int idx = g * 256 + tid;
            int m = idx >> 3, c4 = idx & 7;
            int row = mB + m;
            float4 v = make_float4(0, 0, 0, 0);
            if (row < N_NODES)
                v = *(const float4*)&x[(size_t)row * 128 + c * 32 + c4 * 4];
            As[c4 * 4 + 0][m] = to_tf32(v.x);
            As[c4 * 4 + 1][m] = to_tf32(v.y);
            As[c4 * 4 + 2][m] = to_tf32(v.z);
            As[c4 * 4 + 3][m] = to_tf32(v.w);
        }
#pragma unroll
        for (int g = 0; g < 4; g++) {
            int idx = g * 256 + tid;
            int row = idx >> 5, c4 = idx & 31;
            float4 v = *(const float4*)&W[(size_t)(c * 32 + row) * 128 + c4 * 4];
            uint4 u = make_uint4(to_tf32(v.x), to_tf32(v.y), to_tf32(v.z), to_tf32(v.w));
            *(uint4*)&Bs[row][c4 * 4] = u;
        }
        __syncthreads();
#pragma unroll
        for (int ks = 0; ks < 4; ks++) {
            const int k0 = ks * 8;
            uint32_t a[2][4], bb[8][2];
#pragma unroll
            for (int mt = 0; mt < 2; mt++) {
                a[mt][0] = As[k0 + l4][m0 + mt * 16 + lg];
                a[mt][1] = As[k0 + l4][m0 + mt * 16 + lg + 8];
                a[mt][2] = As[k0 + l4 + 4][m0 + mt * 16 + lg];
                a[mt][3] = As[k0 + l4 + 4][m0 + mt * 16 + lg + 8];
            }
#pragma unroll
            for (int nt = 0; nt < 8; nt++) {
                bb[nt][0] = Bs[k0 + l4][n0 + nt * 8 + lg];
                bb[nt][1] = Bs[k0 + l4 + 4][n0 + nt * 8 + lg];
            }
#pragma unroll
            for (int mt = 0; mt < 2; mt++)
#pragma unroll
                for (int nt = 0; nt < 8; nt++)
                    mma_tf32(acc[mt][nt], a[mt], bb[nt]);
        }
    }

    // direct store with bias (float2 per acc pair)
#pragma unroll
    for (int nt = 0; nt < 8; nt++) {
        int cc = n0 + nt * 8 + 2 * l4;
        float b0 = bias_s[cc], b1 = bias_s[cc + 1];
#pragma unroll
        for (int q = 0; q < 4; q++) {
            int row = mB + m0 + (q >> 1) * 16 + (q & 1) * 8 + lg;
            if (row < N_NODES) {
                int mt = q >> 1, pr = (q & 1) * 2;
                *(float2*)&dstp[(size_t)row * 128 + cc] =
                    make_float2(acc[mt][nt][pr] + b0, acc[mt][nt][pr + 1] + b1);
            }
        }
    }
}

// ---------------- tf32 edge GEMM (K=128, msg only) + time-poly + alpha ----------------
#define EDGE_SMEM (128 * 132 * 4)

__global__ __launch_bounds__(256, 2) void edge_mma_kernel(
    const float* __restrict__ msg, const float* __restrict__ t,
    const float* __restrict__ lu, const float* __restrict__ We)
{
    extern __shared__ uint32_t smu[];
    uint32_t (*As)[132] = (uint32_t(*)[132])smu;               // [32][132]
    uint32_t (*Bs)[132] = (uint32_t(*)[132])(smu + 32 * 132);  // [32][132]
    float (*Es)[132] = (float(*)[132])smu;                      // [128][132] alias

    __shared__ float rel_s[128];
    __shared__ float Ds[7][128];
    __shared__ int srcs[128], dsts[128];

    const int tid = threadIdx.x;
    const int wid = tid >> 5, lane = tid & 31;
    const int l4 = lane & 3, lg = lane >> 2;
    const int e0 = blockIdx.x * 128;
    const int m0 = (wid & 3) * 32;
    const int n0 = (wid >> 2) * 64;

    if (tid < 128) {
        int s = g_src[e0 + tid], d = g_dst[e0 + tid];
        srcs[tid] = s; dsts[tid] = d;
        rel_s[tid] = lu[s] - t[e0 + tid];
#pragma unroll
        for (int j = 0; j < 7; j++) Ds[j][tid] = g_D[j * 128 + tid];
    }

    float acc[2][8][4];
#pragma unroll
    for (int mt = 0; mt < 2; mt++)
#pragma unroll
        for (int nt = 0; nt < 8; nt++)
#pragma unroll
            for (int j = 0; j < 4; j++) acc[mt][nt][j] = 0.0f;

    for (int c = 0; c < 4; c++) {
        __syncthreads();
        // A: msg chunk, transposed, pre-converted to tf32
#pragma unroll
        for (int g = 0; g < 4; g++) {
            int idx = g * 256 + tid;
            int m = idx >> 3, c4 = idx & 7;
            float4 v = *(const float4*)&msg[(size_t)(e0 + m) * 128 + c * 32 + c4 * 4];
            As[c4 * 4 + 0][m] = to_tf32(v.x);
            As[c4 * 4 + 1][m] = to_tf32(v.y);
            As[c4 * 4 + 2][m] = to_tf32(v.z);
            As[c4 * 4 + 3][m] = to_tf32(v.w);
        }
        // B: We rows 128 + c*32 ..
#pragma unroll
        for (int g = 0; g < 4; g++) {
            int idx = g * 256 + tid;
            int row = idx >> 5, c4 = idx & 31;
            float4 v = *(const float4*)&We[(size_t)(128 + c * 32 + row) * 128 + c4 * 4];
            uint4 u = make_uint4(to_tf32(v.x), to_tf32(v.y), to_tf32(v.z), to_tf32(v.w));
            *(uint4*)&Bs[row][c4 * 4] = u;
        }
        __syncthreads();
#pragma unroll
        for (int ks = 0; ks < 4; ks++) {
            const int k0 = ks * 8;
            uint32_t a[2][4], bb[8][2];
#pragma unroll
            for (int mt = 0; mt < 2; mt++) {
                a[mt][0] = As[k0 + l4][m0 + mt * 16 + lg];
                a[mt][1] = As[k0 + l4][m0 + mt * 16 + lg + 8];
                a[mt][2] = As[k0 + l4 + 4][m0 + mt * 16 + lg];
                a[mt][3] = As[k0 + l4 + 4][m0 + mt * 16 + lg + 8];
            }
#pragma unroll
            for (int nt = 0; nt < 8; nt++) {
                bb[nt][0] = Bs[k0 + l4][n0 + nt * 8 + lg];
                bb[nt][1] = Bs[k0 + l4 + 4][n0 + nt * 8 + lg];
            }
#pragma unroll
            for (int mt = 0; mt < 2; mt++)
#pragma unroll
                for (int nt = 0; nt < 8; nt++)
                    mma_tf32(acc[mt][nt], a[mt], bb[nt]);
        }
    }

    // ---- dump accumulators + time-poly into Es ----
    __syncthreads();   // As/Bs reads done before aliasing write
    float relv[4];
    relv[0] = rel_s[m0 + lg];
    relv[1] = rel_s[m0 + lg + 8];
    relv[2] = rel_s[m0 + 16 + lg];
    relv[3] = rel_s[m0 + 16 + lg + 8];
#pragma unroll
    for (int nt = 0; nt < 8; nt++) {
        int cc = n0 + nt * 8 + 2 * l4;
        float C0[7], C1[7];
#pragma unroll
        for (int j = 0; j < 7; j++) { C0[j] = Ds[j][cc]; C1[j] = Ds[j][cc + 1]; }
#pragma unroll
        for (int q = 0; q < 4; q++) {
            float r = relv[q];
            float p0 = C0[6], p1 = C1[6];
#pragma unroll
            for (int j = 5; j >= 0; j--) {
                p0 = fmaf(p0, r, C0[j]);
                p1 = fmaf(p1, r, C1[j]);
            }
            int row = m0 + (q >> 1) * 16 + (q & 1) * 8 + lg;
            int mt = q >> 1, pr = (q & 1) * 2;
            *(float2*)&Es[row][cc] =
                make_float2(acc[mt][nt][pr] + p0, acc[mt][nt][pr + 1] + p1);
        }
    }
    __syncthreads();

    // ---- epilogue: thread -> (edge r, head h) ----
    const int r = tid >> 1, h = tid & 1;
    int snode = srcs[r], dnode = dsts[r];
    const float4* q4 = (const float4*)&g_Q[(size_t)dnode * 128 + h * 64];
    const float4* k4 = (const float4*)&g_K[(size_t)snode * 128 + h * 64];
    const float4* v4 = (const float4*)&g_V[(size_t)snode * 128 + h * 64];
    float4* o4 = (float4*)&g_e[(size_t)(e0 + r) * 128 + h * 64];
    const float* erow = &Es[r][h * 64];
    float s = 0.0f;
#pragma unroll
    for (int c = 0; c < 16; c++) {
        float4 q = q4[c], k = k4[c], v = v4[c];
        float4 ev = *(const float4*)&erow[c * 4];
        s += q.x * (k.x + ev.x) + q.y * (k.y + ev.y) +
             q.z * (k.z + ev.z) + q.w * (k.w + ev.w);
        o4[c] = make_float4(v.x + ev.x, v.y + ev.y, v.z + ev.z, v.w + ev.w);
    }
    s *= 0.125f;
    g_p[(size_t)(e0 + r) * 2 + h] = s;
    int enc = __float_as_int(s);
    enc = (enc < 0) ? (enc ^ 0x7fffffff) : enc;
    atomicMax(&g_m[dnode * 2 + h], enc);
}

// ---------------- exp + segment denom ----------------
__global__ void exp_kernel() {
    int i = blockIdx.x * blockDim.x + threadIdx.x;
    if (i >= E_EDGES * 2) return;
    int e = i >> 1, h = i & 1;
    int d = g_dst[e];
    int enc = g_m[d * 2 + h];
    enc = (enc < 0) ? (enc ^ 0x7fffffff) : enc;
    float mval = __int_as_float(enc);
    float p = __expf(g_p[i] - mval);
    g_p[i] = p;
    atomicAdd(&g_den[d * 2 + h], p);
}

// ---------------- scatter: out[dst] += attn * (v+e) ----------------
__global__ __launch_bounds__(256) void scatter_kernel(float* __restrict__ out) {
    int gw = (blockIdx.x * blockDim.x + threadIdx.x) >> 5;
    int lane = threadIdx.x & 31;
    if (gw >= E_EDGES) return;
    int d = g_dst[gw];
    int h = lane >> 4;
    float attn = g_p[(size_t)gw * 2 + h] / g_den[d * 2 + h];
    float4 ve = *(const float4*)&g_e[(size_t)gw * 128 + lane * 4];
    atomicAdd((float4*)&out[(size_t)d * 128 + lane * 4],
              make_float4(attn * ve.x, attn * ve.y, attn * ve.z, attn * ve.w));
}

// ---------------- launcher ----------------
extern "C" void kernel_launch(void* const* d_in, const int* in_sizes, int n_in,
                              void* d_out, int out_size) {
    const float* x   = (const float*)d_in[0];
    const float* lu  = (const float*)d_in[1];
    const float* t   = (const float*)d_in[2];
    const float* msg = (const float*)d_in[3];
    const int*   eiw = (const int*)d_in[4];
    const float* Wt  = (const float*)d_in[5];
    const float* bt  = (const float*)d_in[6];
    const float* Wq  = (const float*)d_in[7];
    const float* bq  = (const float*)d_in[8];
    const float* Wk  = (const float*)d_in[9];
    const float* bk  = (const float*)d_in[10];
    const float* Wv  = (const float*)d_in[11];
    const float* bv  = (const float*)d_in[12];
    const float* We  = (const float*)d_in[13];
    const float* Ws  = (const float*)d_in[14];
    const float* bs  = (const float*)d_in[15];
    float* out = (float*)d_out;

    cudaFuncSetAttribute(edge_mma_kernel,
                         cudaFuncAttributeMaxDynamicSharedMemorySize, EDGE_SMEM);
    cudaFuncSetAttribute(node_mma_kernel,
                         cudaFuncAttributeMaxDynamicSharedMemorySize, NODE_SMEM);

    detect_kernel<<<1, 256>>>(eiw);
    convert_kernel<<<(E_EDGES + 255) / 256, 256>>>(eiw);
    init_kernel<<<(N_NODES * 2 + 255) / 256, 256>>>();
    prep_D_kernel<<<1, 128>>>(Wt, bt, We);
    node_mma_kernel<<<dim3((N_NODES + 127) / 128, 4), 256, NODE_SMEM>>>(
        x, Wq, bq, Wk, bk, Wv, bv, Ws, bs, out);
    edge_mma_kernel<<<E_EDGES / 128, 256, EDGE_SMEM>>>(msg, t, lu, We);
    exp_kernel<<<(E_EDGES * 2 + 255) / 256, 256>>>();
    scatter_kernel<<<E_EDGES / 8, 256>>>(out);
}

// round 6
// speedup vs baseline: 2.5090x; 1.2947x over previous
#include <cuda_runtime.h>
#include <cuda_fp16.h>
#include <cstdint>

#define N_NODES 50000
#define E_EDGES 800000

// ---------------- device scratch ----------------
__device__ int      g_is64;
__device__ int      g_src[E_EDGES];
__device__ int      g_dst[E_EDGES];
__device__ float    g_Q[(size_t)N_NODES * 128];
__device__ float    g_K[(size_t)N_NODES * 128];
__device__ float    g_V[(size_t)N_NODES * 128];
__device__ uint32_t g_e[(size_t)E_EDGES * 64];   // v[src]+e as half2 (64 per edge)
__device__ float    g_p[(size_t)E_EDGES * 2];
__device__ int      g_m[(size_t)N_NODES * 2];
__device__ float    g_den[(size_t)N_NODES * 2];
__device__ float    g_D[7 * 128];                // time-poly coefficients
__device__ uint32_t g_Bpack[5 * 128 * 72];       // packed fp16 B tiles (Wq,Wk,Wv,Ws,We[128:])

#define BSTRIDE 72   // 32-bit words per packed row (64 half2 + 8 pad)

// ---------------- helpers ----------------
__device__ __forceinline__ uint32_t h2(float a, float b) {
    uint32_t r;
    asm("cvt.rn.f16x2.f32 %0, %2, %1;" : "=r"(r) : "f"(a), "f"(b));
    return r;
}
__device__ __forceinline__ void mma_f16(float* c, const uint32_t* a, const uint32_t* b) {
    asm volatile(
        "mma.sync.aligned.m16n8k16.row.col.f32.f16.f16.f32 "
        "{%0,%1,%2,%3}, {%4,%5,%6,%7}, {%8,%9}, {%0,%1,%2,%3};"
        : "+f"(c[0]), "+f"(c[1]), "+f"(c[2]), "+f"(c[3])
        : "r"(a[0]), "r"(a[1]), "r"(a[2]), "r"(a[3]), "r"(b[0]), "r"(b[1]));
}

// ---------------- edge index handling ----------------
__global__ void detect_kernel(const int* __restrict__ w) {
    __shared__ int any_nz;
    if (threadIdx.x == 0) any_nz = 0;
    __syncthreads();
    int v = 0;
    for (int i = threadIdx.x; i < 2048; i += blockDim.x) v |= w[2 * i + 1];
    if (v) atomicOr(&any_nz, 1);
    __syncthreads();
    if (threadIdx.x == 0) g_is64 = any_nz ? 0 : 1;
}

__global__ void convert_kernel(const int* __restrict__ w) {
    int e = blockIdx.x * blockDim.x + threadIdx.x;
    if (e >= E_EDGES) return;
    if (g_is64) { g_src[e] = w[2 * e]; g_dst[e] = w[2 * (E_EDGES + e)]; }
    else        { g_src[e] = w[e];     g_dst[e] = w[E_EDGES + e]; }
}

__global__ void init_kernel() {
    int i = blockIdx.x * blockDim.x + threadIdx.x;
    if (i < N_NODES * 2) { g_m[i] = (int)0x80000000; g_den[i] = 0.0f; }
}

// ---------------- time-poly coefficients, parallel ----------------
// D[j][n] = sum_k (w_k^j / j!) * cos(b_k + j*pi/2) * We[k][n]
__global__ void prep_D_kernel(const float* __restrict__ Wt,
                              const float* __restrict__ bt,
                              const float* __restrict__ We) {
    __shared__ float sh[128];
    int n = blockIdx.x, k = threadIdx.x;
    float w = Wt[k], b = bt[k];
    float we = We[(size_t)k * 128 + n];
    float cb = cosf(b) * we, sb = sinf(b) * we;
    float base[4] = {cb, -sb, -cb, sb};
    float wj = 1.0f;
    for (int j = 0; j < 7; j++) {
        sh[k] = wj * base[j & 3];
        __syncthreads();
        for (int off = 64; off; off >>= 1) {
            if (k < off) sh[k] += sh[k + off];
            __syncthreads();
        }
        if (k == 0) g_D[j * 128 + n] = sh[0];
        __syncthreads();
        wj *= w / (float)(j + 1);
    }
}

// ---------------- pack B matrices into paired-k fp16 layout ----------------
// packed[n*72 + perm(kp)] = half2(W[2kp][n], W[2kp+1][n]); perm makes
// fragment loads (kp = ks*8+l4, ks*8+l4+4) adjacent for LDS.64.
__global__ void prep_pack_kernel(
    const float* __restrict__ Wq, const float* __restrict__ Wk,
    const float* __restrict__ Wv, const float* __restrict__ Ws,
    const float* __restrict__ We)
{
    int mat = blockIdx.y;
    const float* W;
    int rowbase = 0;
    switch (mat) {
        case 0: W = Wq; break;
        case 1: W = Wk; break;
        case 2: W = Wv; break;
        case 3: W = Ws; break;
        default: W = We; rowbase = 128; break;
    }
    int idx = blockIdx.x * 256 + threadIdx.x;   // 0..9215
    if (idx >= 128 * BSTRIDE) return;
    int n = idx / BSTRIDE, s = idx % BSTRIDE;
    uint32_t val = 0;
    if (s < 64) {
        int kp = ((s >> 3) << 3) + ((s & 1) << 2) + ((s & 7) >> 1);  // inverse perm
        float v0 = W[(size_t)(rowbase + 2 * kp) * 128 + n];
        float v1 = W[(size_t)(rowbase + 2 * kp + 1) * 128 + n];
        val = h2(v0, v1);
    }
    g_Bpack[(size_t)mat * 128 * BSTRIDE + idx] = val;
}

// ---------------- fp16 node GEMM: [N,128]@[128,128] + bias, x4 ----------------
#define TILE_SMEM (2 * 128 * BSTRIDE * 4)

__global__ __launch_bounds__(256, 2) void node_mma_kernel(
    const float* __restrict__ x,
    const float* __restrict__ bq, const float* __restrict__ bk,
    const float* __restrict__ bv, const float* __restrict__ bs,
    float* __restrict__ out)
{
    extern __shared__ uint32_t smu[];
    uint32_t* Aw = smu;
    uint32_t* Bw = smu + 128 * BSTRIDE;
    __shared__ float bias_s[128];

    const float* b; float* dstp;
    switch (blockIdx.y) {
        case 0: b = bq; dstp = g_Q; break;
        case 1: b = bk; dstp = g_K; break;
        case 2: b = bv; dstp = g_V; break;
        default: b = bs; dstp = out; break;
    }

    const int tid = threadIdx.x;
    const int wid = tid >> 5, lane = tid & 31;
    const int l4 = lane & 3, lg = lane >> 2;
    const int mB = blockIdx.x * 128;
    const int m0 = (wid & 3) * 32;
    const int n0 = (wid >> 2) * 64;

    if (tid < 128) bias_s[tid] = b[tid];

    // A fill: x tile -> paired-k fp16
#pragma unroll
    for (int g = 0; g < 16; g++) {
        int idx = g * 256 + tid;
        int m = idx >> 5, c8 = idx & 31;
        int row = mB + m;
        float4 v = make_float4(0, 0, 0, 0);
        if (row < N_NODES) v = *(const float4*)&x[(size_t)row * 128 + c8 * 4];
        int p0 = ((c8 >> 2) << 3) + ((c8 & 1) << 2) + ((c8 >> 1) & 1);
        Aw[m * BSTRIDE + p0]     = h2(v.x, v.y);
        Aw[m * BSTRIDE + p0 + 2] = h2(v.z, v.w);
    }
    // B fill: straight copy of packed weights
    {
        const uint4* src = (const uint4*)&g_Bpack[(size_t)blockIdx.y * 128 * BSTRIDE];
        uint4* dst = (uint4*)Bw;
#pragma unroll
        for (int g = 0; g < 9; g++) dst[g * 256 + tid] = src[g * 256 + tid];
    }
    __syncthreads();

    float acc[2][8][4];
#pragma unroll
    for (int mt = 0; mt < 2; mt++)
#pragma unroll
        for (int nt = 0; nt < 8; nt++)
#pragma unroll
            for (int j = 0; j < 4; j++) acc[mt][nt][j] = 0.0f;

#pragma unroll
    for (int ks = 0; ks < 8; ks++) {
        const int ko = ks * 8 + 2 * l4;
        uint2 av[2][2], bv2[8];
#pragma unroll
        for (int mt = 0; mt < 2; mt++) {
            av[mt][0] = *(const uint2*)&Aw[(m0 + mt * 16 + lg) * BSTRIDE + ko];
            av[mt][1] = *(const uint2*)&Aw[(m0 + mt * 16 + lg + 8) * BSTRIDE + ko];
        }
#pragma unroll
        for (int nt = 0; nt < 8; nt++)
            bv2[nt] = *(const uint2*)&Bw[(n0 + nt * 8 + lg) * BSTRIDE + ko];
#pragma unroll
        for (int mt = 0; mt < 2; mt++) {
            uint32_t a[4] = {av[mt][0].x, av[mt][1].x, av[mt][0].y, av[mt][1].y};
#pragma unroll
            for (int nt = 0; nt < 8; nt++)
                mma_f16(acc[mt][nt], a, (const uint32_t*)&bv2[nt]);
        }
    }

    // store with bias
#pragma unroll
    for (int nt = 0; nt < 8; nt++) {
        int cc = n0 + nt * 8 + 2 * l4;
        float b0 = bias_s[cc], b1 = bias_s[cc + 1];
#pragma unroll
        for (int q = 0; q < 4; q++) {
            int row = mB + m0 + (q >> 1) * 16 + (q & 1) * 8 + lg;
            if (row < N_NODES) {
                int mt = q >> 1, pr = (q & 1) * 2;
                *(float2*)&dstp[(size_t)row * 128 + cc] =
                    make_float2(acc[mt][nt][pr] + b0, acc[mt][nt][pr + 1] + b1);
            }
        }
    }
}

// ---------------- fp16 edge GEMM (K=128 msg) + time-poly + alpha ----------------
__global__ __launch_bounds__(256, 2) void edge_mma_kernel(
    const float* __restrict__ msg, const float* __restrict__ t,
    const float* __restrict__ lu)
{
    extern __shared__ uint32_t smu[];
    uint32_t* Aw = smu;
    uint32_t* Bw = smu + 128 * BSTRIDE;
    float (*Es)[132] = (float(*)[132])smu;   // aliases A+B after k-loop

    __shared__ float rel_s[128];
    __shared__ float Ds[7][128];
    __shared__ int srcs[128], dsts[128];

    const int tid = threadIdx.x;
    const int wid = tid >> 5, lane = tid & 31;
    const int l4 = lane & 3, lg = lane >> 2;
    const int e0 = blockIdx.x * 128;
    const int m0 = (wid & 3) * 32;
    const int n0 = (wid >> 2) * 64;

    if (tid < 128) {
        int s = g_src[e0 + tid], d = g_dst[e0 + tid];
        srcs[tid] = s; dsts[tid] = d;
        rel_s[tid] = lu[s] - t[e0 + tid];
#pragma unroll
        for (int j = 0; j < 7; j++) Ds[j][tid] = g_D[j * 128 + tid];
    }

    // A fill: msg tile -> paired-k fp16
#pragma unroll
    for (int g = 0; g < 16; g++) {
        int idx = g * 256 + tid;
        int m = idx >> 5, c8 = idx & 31;
        float4 v = *(const float4*)&msg[(size_t)(e0 + m) * 128 + c8 * 4];
        int p0 = ((c8 >> 2) << 3) + ((c8 & 1) << 2) + ((c8 >> 1) & 1);
        Aw[m * BSTRIDE + p0]     = h2(v.x, v.y);
        Aw[m * BSTRIDE + p0 + 2] = h2(v.z, v.w);
    }
    // B fill: packed We lower half (mat index 4)
    {
        const uint4* src = (const uint4*)&g_Bpack[(size_t)4 * 128 * BSTRIDE];
        uint4* dst = (uint4*)Bw;
#pragma unroll
        for (int g = 0; g < 9; g++) dst[g * 256 + tid] = src[g * 256 + tid];
    }
    __syncthreads();

    float acc[2][8][4];
#pragma unroll
    for (int mt = 0; mt < 2; mt++)
#pragma unroll
        for (int nt = 0; nt < 8; nt++)
#pragma unroll
            for (int j = 0; j < 4; j++) acc[mt][nt][j] = 0.0f;

#pragma unroll
    for (int ks = 0; ks < 8; ks++) {
        const int ko = ks * 8 + 2 * l4;
        uint2 av[2][2], bv2[8];
#pragma unroll
        for (int mt = 0; mt < 2; mt++) {
            av[mt][0] = *(const uint2*)&Aw[(m0 + mt * 16 + lg) * BSTRIDE + ko];
            av[mt][1] = *(const uint2*)&Aw[(m0 + mt * 16 + lg + 8) * BSTRIDE + ko];
        }
#pragma unroll
        for (int nt = 0; nt < 8; nt++)
            bv2[nt] = *(const uint2*)&Bw[(n0 + nt * 8 + lg) * BSTRIDE + ko];
#pragma unroll
        for (int mt = 0; mt < 2; mt++) {
            uint32_t a[4] = {av[mt][0].x, av[mt][1].x, av[mt][0].y, av[mt][1].y};
#pragma unroll
            for (int nt = 0; nt < 8; nt++)
                mma_f16(acc[mt][nt], a, (const uint32_t*)&bv2[nt]);
        }
    }

    // ---- dump accumulators + time-poly into Es ----
    __syncthreads();  // A/B reads done before aliasing write
    float relv[4];
    relv[0] = rel_s[m0 + lg];
    relv[1] = rel_s[m0 + lg + 8];
    relv[2] = rel_s[m0 + 16 + lg];
    relv[3] = rel_s[m0 + 16 + lg + 8];
#pragma unroll
    for (int nt = 0; nt < 8; nt++) {
        int cc = n0 + nt * 8 + 2 * l4;
        float C0[7], C1[7];
#pragma unroll
        for (int j = 0; j < 7; j++) { C0[j] = Ds[j][cc]; C1[j] = Ds[j][cc + 1]; }
#pragma unroll
        for (int q = 0; q < 4; q++) {
            float r = relv[q];
            float p0 = C0[6], p1 = C1[6];
#pragma unroll
            for (int j = 5; j >= 0; j--) {
                p0 = fmaf(p0, r, C0[j]);
                p1 = fmaf(p1, r, C1[j]);
            }
            int row = m0 + (q >> 1) * 16 + (q & 1) * 8 + lg;
            int mt = q >> 1, pr = (q & 1) * 2;
            *(float2*)&Es[row][cc] =
                make_float2(acc[mt][nt][pr] + p0, acc[mt][nt][pr + 1] + p1);
        }
    }
    __syncthreads();

    // ---- epilogue: thread -> (edge r, head h) ----
    const int r = tid >> 1, h = tid & 1;
    int snode = srcs[r], dnode = dsts[r];
    const float4* q4 = (const float4*)&g_Q[(size_t)dnode * 128 + h * 64];
    const float4* k4 = (const float4*)&g_K[(size_t)snode * 128 + h * 64];
    const float4* v4 = (const float4*)&g_V[(size_t)snode * 128 + h * 64];
    uint32_t* ge = &g_e[(size_t)(e0 + r) * 64 + h * 32];
    const float* erow = &Es[r][h * 64];
    float s = 0.0f;
#pragma unroll
    for (int c = 0; c < 16; c++) {
        float4 q = q4[c], k = k4[c], v = v4[c];
        float4 ev = *(const float4*)&erow[c * 4];
        float ax = v.x + ev.x, ay = v.y + ev.y, az = v.z + ev.z, aw = v.w + ev.w;
        s += q.x * (k.x + ev.x) + q.y * (k.y + ev.y) +
             q.z * (k.z + ev.z) + q.w * (k.w + ev.w);
        *(uint2*)&ge[c * 2] = make_uint2(h2(ax, ay), h2(az, aw));
    }
    s *= 0.125f;
    g_p[(size_t)(e0 + r) * 2 + h] = s;
    int enc = __float_as_int(s);
    enc = (enc < 0) ? (enc ^ 0x7fffffff) : enc;
    atomicMax(&g_m[dnode * 2 + h], enc);
}

// ---------------- exp + segment denom ----------------
__global__ void exp_kernel() {
    int i = blockIdx.x * blockDim.x + threadIdx.x;
    if (i >= E_EDGES * 2) return;
    int e = i >> 1, h = i & 1;
    int d = g_dst[e];
    int enc = g_m[d * 2 + h];
    enc = (enc < 0) ? (enc ^ 0x7fffffff) : enc;
    float mval = __int_as_float(enc);
    float p = __expf(g_p[i] - mval);
    g_p[i] = p;
    atomicAdd(&g_den[d * 2 + h], p);
}

// ---------------- scatter: out[dst] += attn * (v+e) ----------------
__global__ __launch_bounds__(256) void scatter_kernel(float* __restrict__ out) {
    int gw = (blockIdx.x * blockDim.x + threadIdx.x) >> 5;
    int lane = threadIdx.x & 31;
    if (gw >= E_EDGES) return;
    int d = g_dst[gw];
    int h = lane >> 4;
    float attn = g_p[(size_t)gw * 2 + h] / g_den[d * 2 + h];
    uint2 u = *(const uint2*)&g_e[(size_t)gw * 64 + lane * 2];
    float2 p0 = __half22float2(*(__half2*)&u.x);
    float2 p1 = __half22float2(*(__half2*)&u.y);
    atomicAdd((float4*)&out[(size_t)d * 128 + lane * 4],
              make_float4(attn * p0.x, attn * p0.y, attn * p1.x, attn * p1.y));
}

// ---------------- launcher ----------------
extern "C" void kernel_launch(void* const* d_in, const int* in_sizes, int n_in,
                              void* d_out, int out_size) {
    const float* x   = (const float*)d_in[0];
    const float* lu  = (const float*)d_in[1];
    const float* t   = (const float*)d_in[2];
    const float* msg = (const float*)d_in[3];
    const int*   eiw = (const int*)d_in[4];
    const float* Wt  = (const float*)d_in[5];
    const float* bt  = (const float*)d_in[6];
    const float* Wq  = (const float*)d_in[7];
    const float* bq  = (const float*)d_in[8];
    const float* Wk  = (const float*)d_in[9];
    const float* bk  = (const float*)d_in[10];
    const float* Wv  = (const float*)d_in[11];
    const float* bv  = (const float*)d_in[12];
    const float* We  = (const float*)d_in[13];
    const float* Ws  = (const float*)d_in[14];
    const float* bs  = (const float*)d_in[15];
    float* out = (float*)d_out;

    cudaFuncSetAttribute(edge_mma_kernel,
                         cudaFuncAttributeMaxDynamicSharedMemorySize, TILE_SMEM);
    cudaFuncSetAttribute(node_mma_kernel,
                         cudaFuncAttributeMaxDynamicSharedMemorySize, TILE_SMEM);

    detect_kernel<<<1, 256>>>(eiw);
    convert_kernel<<<(E_EDGES + 255) / 256, 256>>>(eiw);
    init_kernel<<<(N_NODES * 2 + 255) / 256, 256>>>();
    prep_D_kernel<<<128, 128>>>(Wt, bt, We);
    prep_pack_kernel<<<dim3(36, 5), 256>>>(Wq, Wk, Wv, Ws, We);
    node_mma_kernel<<<dim3((N_NODES + 127) / 128, 4), 256, TILE_SMEM>>>(
        x, bq, bk, bv, bs, out);
    edge_mma_kernel<<<E_EDGES / 128, 256, TILE_SMEM>>>(msg, t, lu);
    exp_kernel<<<(E_EDGES * 2 + 255) / 256, 256>>>();
    scatter_kernel<<<E_EDGES / 8, 256>>>(out);
}

// round 7
// speedup vs baseline: 3.0718x; 1.2243x over previous
#include <cuda_runtime.h>
#include <cuda_fp16.h>
#include <cstdint>

#define N_NODES 50000
#define E_EDGES 800000
#define BSTRIDE 72   // 32-bit words per packed row (64 half2 + 8 pad)

// ---------------- device scratch ----------------
__device__ int      g_is64;
__device__ int      g_src[E_EDGES];
__device__ int      g_dst[E_EDGES];
__device__ int      g_hist[N_NODES];
__device__ int      g_off[N_NODES + 1];
__device__ int      g_cur[N_NODES];
__device__ int      g_eid[E_EDGES];
__device__ float    g_Q[(size_t)N_NODES * 128];
__device__ float    g_K[(size_t)N_NODES * 128];
__device__ uint32_t g_Vh[(size_t)N_NODES * 64];   // V as half2
__device__ uint32_t g_e[(size_t)E_EDGES * 64];    // v[src]+e as half2
__device__ float    g_p[(size_t)E_EDGES * 2];     // alpha
__device__ float    g_D[7 * 128];                 // time-poly coefficients
__device__ uint32_t g_Bpack[5 * 128 * BSTRIDE];   // packed fp16 weights

// ---------------- helpers ----------------
__device__ __forceinline__ uint32_t h2(float a, float b) {
    uint32_t r;
    asm("cvt.rn.f16x2.f32 %0, %2, %1;" : "=r"(r) : "f"(a), "f"(b));
    return r;
}
__device__ __forceinline__ float2 uh2f(uint32_t u) {
    return __half22float2(*(__half2*)&u);
}
__device__ __forceinline__ uint32_t uhadd2(uint32_t a, uint32_t b) {
    __half2 r = __hadd2(*(__half2*)&a, *(__half2*)&b);
    return *(uint32_t*)&r;
}
__device__ __forceinline__ void mma_f16(float* c, const uint32_t* a, const uint32_t* b) {
    asm volatile(
        "mma.sync.aligned.m16n8k16.row.col.f32.f16.f16.f32 "
        "{%0,%1,%2,%3}, {%4,%5,%6,%7}, {%8,%9}, {%0,%1,%2,%3};"
        : "+f"(c[0]), "+f"(c[1]), "+f"(c[2]), "+f"(c[3])
        : "r"(a[0]), "r"(a[1]), "r"(a[2]), "r"(a[3]), "r"(b[0]), "r"(b[1]));
}

// ---------------- edge index handling + CSR build ----------------
__global__ void detect_kernel(const int* __restrict__ w) {
    __shared__ int any_nz;
    if (threadIdx.x == 0) any_nz = 0;
    __syncthreads();
    int v = 0;
    for (int i = threadIdx.x; i < 2048; i += blockDim.x) v |= w[2 * i + 1];
    if (v) atomicOr(&any_nz, 1);
    __syncthreads();
    if (threadIdx.x == 0) g_is64 = any_nz ? 0 : 1;
}

__global__ void zero_hist_kernel() {
    int i = blockIdx.x * blockDim.x + threadIdx.x;
    if (i < N_NODES) g_hist[i] = 0;
}

__global__ void convert_kernel(const int* __restrict__ w) {
    int e = blockIdx.x * blockDim.x + threadIdx.x;
    if (e >= E_EDGES) return;
    int s, d;
    if (g_is64) { s = w[2 * e]; d = w[2 * (E_EDGES + e)]; }
    else        { s = w[e];     d = w[E_EDGES + e]; }
    g_src[e] = s;
    g_dst[e] = d;
    atomicAdd(&g_hist[d], 1);
}

__global__ void scan_kernel() {   // single block, 1024 threads
    __shared__ int part[1024];
    const int CH = 49;            // 1024*49 >= 50000
    int tid = threadIdx.x;
    int base = tid * CH;
    int s = 0;
    for (int j = 0; j < CH; j++) {
        int idx = base + j;
        if (idx < N_NODES) s += g_hist[idx];
    }
    part[tid] = s;
    __syncthreads();
    for (int off = 1; off < 1024; off <<= 1) {
        int v = (tid >= off) ? part[tid - off] : 0;
        __syncthreads();
        part[tid] += v;
        __syncthreads();
    }
    int run = part[tid] - s;
    for (int j = 0; j < CH; j++) {
        int idx = base + j;
        if (idx < N_NODES) {
            g_off[idx] = run;
            g_cur[idx] = run;
            run += g_hist[idx];
        }
    }
    if (tid == 1023) g_off[N_NODES] = part[1023];
}

__global__ void permute_kernel() {
    int e = blockIdx.x * blockDim.x + threadIdx.x;
    if (e >= E_EDGES) return;
    int pos = atomicAdd(&g_cur[g_dst[e]], 1);
    g_eid[pos] = e;
}

// ---------------- time-poly coefficients ----------------
__global__ void prep_D_kernel(const float* __restrict__ Wt,
                              const float* __restrict__ bt,
                              const float* __restrict__ We) {
    __shared__ float sh[128];
    int n = blockIdx.x, k = threadIdx.x;
    float w = Wt[k], b = bt[k];
    float we = We[(size_t)k * 128 + n];
    float cb = cosf(b) * we, sb = sinf(b) * we;
    float base[4] = {cb, -sb, -cb, sb};
    float wj = 1.0f;
    for (int j = 0; j < 7; j++) {
        sh[k] = wj * base[j & 3];
        __syncthreads();
        for (int off = 64; off; off >>= 1) {
            if (k < off) sh[k] += sh[k + off];
            __syncthreads();
        }
        if (k == 0) g_D[j * 128 + n] = sh[0];
        __syncthreads();
        wj *= w / (float)(j + 1);
    }
}

// ---------------- pack weights into paired-k fp16 layout ----------------
__global__ void prep_pack_kernel(
    const float* __restrict__ Wq, const float* __restrict__ Wk,
    const float* __restrict__ Wv, const float* __restrict__ Ws,
    const float* __restrict__ We)
{
    int mat = blockIdx.y;
    const float* W;
    int rowbase = 0;
    switch (mat) {
        case 0: W = Wq; break;
        case 1: W = Wk; break;
        case 2: W = Wv; break;
        case 3: W = Ws; break;
        default: W = We; rowbase = 128; break;
    }
    int idx = blockIdx.x * 256 + threadIdx.x;
    if (idx >= 128 * BSTRIDE) return;
    int n = idx / BSTRIDE, s = idx % BSTRIDE;
    uint32_t val = 0;
    if (s < 64) {
        int kp = ((s >> 3) << 3) + ((s & 1) << 2) + ((s & 7) >> 1);
        float v0 = W[(size_t)(rowbase + 2 * kp) * 128 + n];
        float v1 = W[(size_t)(rowbase + 2 * kp + 1) * 128 + n];
        val = h2(v0, v1);
    }
    g_Bpack[(size_t)mat * 128 * BSTRIDE + idx] = val;
}

// ---------------- fp16 node GEMM: [N,128]@[128,128] + bias, x4 ----------------
#define TILE_SMEM (2 * 128 * BSTRIDE * 4)

__global__ __launch_bounds__(256, 2) void node_mma_kernel(
    const float* __restrict__ x,
    const float* __restrict__ bq, const float* __restrict__ bk,
    const float* __restrict__ bv, const float* __restrict__ bs,
    float* __restrict__ out)
{
    extern __shared__ uint32_t smu[];
    uint32_t* Aw = smu;
    uint32_t* Bw = smu + 128 * BSTRIDE;
    __shared__ float bias_s[128];

    const float* b; float* dstp;
    switch (blockIdx.y) {
        case 0: b = bq; dstp = g_Q; break;
        case 1: b = bk; dstp = g_K; break;
        case 2: b = bv; dstp = nullptr; break;  // -> g_Vh fp16
        default: b = bs; dstp = out; break;
    }

    const int tid = threadIdx.x;
    const int wid = tid >> 5, lane = tid & 31;
    const int l4 = lane & 3, lg = lane >> 2;
    const int mB = blockIdx.x * 128;
    const int m0 = (wid & 3) * 32;
    const int n0 = (wid >> 2) * 64;

    if (tid < 128) bias_s[tid] = b[tid];

#pragma unroll
    for (int g = 0; g < 16; g++) {
        int idx = g * 256 + tid;
        int m = idx >> 5, c8 = idx & 31;
        int row = mB + m;
        float4 v = make_float4(0, 0, 0, 0);
        if (row < N_NODES) v = *(const float4*)&x[(size_t)row * 128 + c8 * 4];
        int p0 = ((c8 >> 2) << 3) + ((c8 & 1) << 2) + ((c8 >> 1) & 1);
        Aw[m * BSTRIDE + p0]     = h2(v.x, v.y);
        Aw[m * BSTRIDE + p0 + 2] = h2(v.z, v.w);
    }
    {
        const uint4* src = (const uint4*)&g_Bpack[(size_t)blockIdx.y * 128 * BSTRIDE];
        uint4* dst = (uint4*)Bw;
#pragma unroll
        for (int g = 0; g < 9; g++) dst[g * 256 + tid] = src[g * 256 + tid];
    }
    __syncthreads();

    float acc[2][8][4];
#pragma unroll
    for (int mt = 0; mt < 2; mt++)
#pragma unroll
        for (int nt = 0; nt < 8; nt++)
#pragma unroll
            for (int j = 0; j < 4; j++) acc[mt][nt][j] = 0.0f;

#pragma unroll
    for (int ks = 0; ks < 8; ks++) {
        const int ko = ks * 8 + 2 * l4;
        uint2 av[2][2], bv2[8];
#pragma unroll
        for (int mt = 0; mt < 2; mt++) {
            av[mt][0] = *(const uint2*)&Aw[(m0 + mt * 16 + lg) * BSTRIDE + ko];
            av[mt][1] = *(const uint2*)&Aw[(m0 + mt * 16 + lg + 8) * BSTRIDE + ko];
        }
#pragma unroll
        for (int nt = 0; nt < 8; nt++)
            bv2[nt] = *(const uint2*)&Bw[(n0 + nt * 8 + lg) * BSTRIDE + ko];
#pragma unroll
        for (int mt = 0; mt < 2; mt++) {
            uint32_t a[4] = {av[mt][0].x, av[mt][1].x, av[mt][0].y, av[mt][1].y};
#pragma unroll
            for (int nt = 0; nt < 8; nt++)
                mma_f16(acc[mt][nt], a, (const uint32_t*)&bv2[nt]);
        }
    }

#pragma unroll
    for (int nt = 0; nt < 8; nt++) {
        int cc = n0 + nt * 8 + 2 * l4;
        float b0 = bias_s[cc], b1 = bias_s[cc + 1];
#pragma unroll
        for (int q = 0; q < 4; q++) {
            int row = mB + m0 + (q >> 1) * 16 + (q & 1) * 8 + lg;
            if (row >= N_NODES) continue;
            int mt = q >> 1, pr = (q & 1) * 2;
            float o0 = acc[mt][nt][pr] + b0, o1 = acc[mt][nt][pr + 1] + b1;
            if (blockIdx.y == 2)
                g_Vh[(size_t)row * 64 + (cc >> 1)] = h2(o0, o1);
            else
                *(float2*)&dstp[(size_t)row * 128 + cc] = make_float2(o0, o1);
        }
    }
}

// ---------------- fp16 edge GEMM (256 edges/CTA) + time-poly + alpha ----------------
__global__ __launch_bounds__(256, 2) void edge_mma_kernel(
    const float* __restrict__ msg, const float* __restrict__ t,
    const float* __restrict__ lu)
{
    extern __shared__ uint32_t smu[];
    uint32_t* Bw = smu;                       // persists both halves
    uint32_t* Aw = smu + 128 * BSTRIDE;       // overwritten by Es after mma
    uint32_t* Esh = Aw;                       // [128][68] half2, stride 68

    __shared__ float rel_s[256];
    __shared__ float Ds[7][128];
    __shared__ int srcs[256], dsts[256];

    const int tid = threadIdx.x;
    const int wid = tid >> 5, lane = tid & 31;
    const int l4 = lane & 3, lg = lane >> 2;
    const int e0 = blockIdx.x * 256;
    const int m0 = (wid & 3) * 32;
    const int n0 = (wid >> 2) * 64;

    {
        int s = g_src[e0 + tid], d = g_dst[e0 + tid];
        srcs[tid] = s; dsts[tid] = d;
        rel_s[tid] = lu[s] - t[e0 + tid];
        if (tid < 128) {
#pragma unroll
            for (int j = 0; j < 7; j++) Ds[j][tid] = g_D[j * 128 + tid];
        }
    }
    // B fill once
    {
        const uint4* src = (const uint4*)&g_Bpack[(size_t)4 * 128 * BSTRIDE];
        uint4* dst = (uint4*)Bw;
#pragma unroll
        for (int g = 0; g < 9; g++) dst[g * 256 + tid] = src[g * 256 + tid];
    }

    for (int half = 0; half < 2; half++) {
        const int eh = e0 + half * 128;
        __syncthreads();   // prior epilogue Es reads done / B+indices ready
        // A fill
#pragma unroll
        for (int g = 0; g < 16; g++) {
            int idx = g * 256 + tid;
            int m = idx >> 5, c8 = idx & 31;
            float4 v = *(const float4*)&msg[(size_t)(eh + m) * 128 + c8 * 4];
            int p0 = ((c8 >> 2) << 3) + ((c8 & 1) << 2) + ((c8 >> 1) & 1);
            Aw[m * BSTRIDE + p0]     = h2(v.x, v.y);
            Aw[m * BSTRIDE + p0 + 2] = h2(v.z, v.w);
        }
        __syncthreads();

        float acc[2][8][4];
#pragma unroll
        for (int mt = 0; mt < 2; mt++)
#pragma unroll
            for (int nt = 0; nt < 8; nt++)
#pragma unroll
                for (int j = 0; j < 4; j++) acc[mt][nt][j] = 0.0f;

#pragma unroll
        for (int ks = 0; ks < 8; ks++) {
            const int ko = ks * 8 + 2 * l4;
            uint2 av[2][2], bv2[8];
#pragma unroll
            for (int mt = 0; mt < 2; mt++) {
                av[mt][0] = *(const uint2*)&Aw[(m0 + mt * 16 + lg) * BSTRIDE + ko];
                av[mt][1] = *(const uint2*)&Aw[(m0 + mt * 16 + lg + 8) * BSTRIDE + ko];
            }
#pragma unroll
            for (int nt = 0; nt < 8; nt++)
                bv2[nt] = *(const uint2*)&Bw[(n0 + nt * 8 + lg) * BSTRIDE + ko];
#pragma unroll
            for (int mt = 0; mt < 2; mt++) {
                uint32_t a[4] = {av[mt][0].x, av[mt][1].x, av[mt][0].y, av[mt][1].y};
#pragma unroll
                for (int nt = 0; nt < 8; nt++)
                    mma_f16(acc[mt][nt], a, (const uint32_t*)&bv2[nt]);
            }
        }
        __syncthreads();  // all Aw reads done before Es overwrite

        // dump acc + time-poly -> Esh (fp16)
        float relv[4];
        relv[0] = rel_s[half * 128 + m0 + lg];
        relv[1] = rel_s[half * 128 + m0 + lg + 8];
        relv[2] = rel_s[half * 128 + m0 + 16 + lg];
        relv[3] = rel_s[half * 128 + m0 + 16 + lg + 8];
#pragma unroll
        for (int nt = 0; nt < 8; nt++) {
            int cc = n0 + nt * 8 + 2 * l4;
            float C0[7], C1[7];
#pragma unroll
            for (int j = 0; j < 7; j++) { C0[j] = Ds[j][cc]; C1[j] = Ds[j][cc + 1]; }
#pragma unroll
            for (int q = 0; q < 4; q++) {
                float r = relv[q];
                float p0 = C0[6], p1 = C1[6];
#pragma unroll
                for (int j = 5; j >= 0; j--) {
                    p0 = fmaf(p0, r, C0[j]);
                    p1 = fmaf(p1, r, C1[j]);
                }
                int row = m0 + (q >> 1) * 16 + (q & 1) * 8 + lg;
                int mt = q >> 1, pr = (q & 1) * 2;
                Esh[row * 68 + (cc >> 1)] =
                    h2(acc[mt][nt][pr] + p0, acc[mt][nt][pr + 1] + p1);
            }
        }
        __syncthreads();

        // epilogue: thread -> (edge r, head h)
        const int r = tid >> 1, h = tid & 1;
        const int li = half * 128 + r;
        int snode = srcs[li], dnode = dsts[li];
        const float4* q4 = (const float4*)&g_Q[(size_t)dnode * 128 + h * 64];
        const float4* k4 = (const float4*)&g_K[(size_t)snode * 128 + h * 64];
        const uint4* v4 = (const uint4*)&g_Vh[(size_t)snode * 64 + h * 32];
        uint4* ge = (uint4*)&g_e[(size_t)(eh + r) * 64 + h * 32];
        const uint32_t* es = &Esh[r * 68 + h * 32];
        float s = 0.0f;
#pragma unroll
        for (int c = 0; c < 8; c++) {
            float4 q0 = q4[2 * c], q1 = q4[2 * c + 1];
            float4 k0 = k4[2 * c], k1 = k4[2 * c + 1];
            uint4 vv = v4[c];
            uint4 ee = *(const uint4*)&es[c * 4];
            float2 e0f = uh2f(ee.x), e1f = uh2f(ee.y), e2f = uh2f(ee.z), e3f = uh2f(ee.w);
            s += q0.x * (k0.x + e0f.x) + q0.y * (k0.y + e0f.y) +
                 q0.z * (k0.z + e1f.x) + q0.w * (k0.w + e1f.y) +
                 q1.x * (k1.x + e2f.x) + q1.y * (k1.y + e2f.y) +
                 q1.z * (k1.z + e3f.x) + q1.w * (k1.w + e3f.y);
            uint4 veu;
            veu.x = uhadd2(vv.x, ee.x);
            veu.y = uhadd2(vv.y, ee.y);
            veu.z = uhadd2(vv.z, ee.z);
            veu.w = uhadd2(vv.w, ee.w);
            ge[c] = veu;
        }
        g_p[(size_t)(eh + r) * 2 + h] = s * 0.125f;
    }
}

// ---------------- aggregation: warp per destination node, no atomics ----------------
__global__ __launch_bounds__(256) void agg_kernel(float* __restrict__ out) {
    int node = (blockIdx.x * blockDim.x + threadIdx.x) >> 5;
    int lane = threadIdx.x & 31;
    if (node >= N_NODES) return;
    int beg = g_off[node], end = g_off[node + 1];
    if (beg == end) return;
    int h = lane >> 4;
    int sl = lane & 15;

    // pass 1: per-head max
    float m = -1e30f;
    for (int i = beg + sl; i < end; i += 16)
        m = fmaxf(m, g_p[(size_t)g_eid[i] * 2 + h]);
#pragma unroll
    for (int off = 1; off < 16; off <<= 1)
        m = fmaxf(m, __shfl_xor_sync(0xFFFFFFFF, m, off));
    // pass 2: denominator
    float den = 0.0f;
    for (int i = beg + sl; i < end; i += 16)
        den += __expf(g_p[(size_t)g_eid[i] * 2 + h] - m);
#pragma unroll
    for (int off = 1; off < 16; off <<= 1)
        den += __shfl_xor_sync(0xFFFFFFFF, den, off);
    float rden = 1.0f / den;

    // pass 3: weighted accumulation (lane owns cols lane*4..lane*4+3)
    float a0 = 0, a1 = 0, a2 = 0, a3 = 0;
    for (int i = beg; i < end; i++) {
        int e = g_eid[i];
        float attn = __expf(g_p[(size_t)e * 2 + h] - m) * rden;
        uint2 u = *(const uint2*)&g_e[(size_t)e * 64 + lane * 2];
        float2 p0 = uh2f(u.x), p1 = uh2f(u.y);
        a0 = fmaf(attn, p0.x, a0);
        a1 = fmaf(attn, p0.y, a1);
        a2 = fmaf(attn, p1.x, a2);
        a3 = fmaf(attn, p1.y, a3);
    }
    float4* orow = (float4*)&out[(size_t)node * 128 + lane * 4];
    float4 o = *orow;
    o.x += a0; o.y += a1; o.z += a2; o.w += a3;
    *orow = o;
}

// ---------------- launcher ----------------
extern "C" void kernel_launch(void* const* d_in, const int* in_sizes, int n_in,
                              void* d_out, int out_size) {
    const float* x   = (const float*)d_in[0];
    const float* lu  = (const float*)d_in[1];
    const float* t   = (const float*)d_in[2];
    const float* msg = (const float*)d_in[3];
    const int*   eiw = (const int*)d_in[4];
    const float* Wt  = (const float*)d_in[5];
    const float* bt  = (const float*)d_in[6];
    const float* Wq  = (const float*)d_in[7];
    const float* bq  = (const float*)d_in[8];
    const float* Wk  = (const float*)d_in[9];
    const float* bk  = (const float*)d_in[10];
    const float* Wv  = (const float*)d_in[11];
    const float* bv  = (const float*)d_in[12];
    const float* We  = (const float*)d_in[13];
    const float* Ws  = (const float*)d_in[14];
    const float* bs  = (const float*)d_in[15];
    float* out = (float*)d_out;

    cudaFuncSetAttribute(edge_mma_kernel,
                         cudaFuncAttributeMaxDynamicSharedMemorySize, TILE_SMEM);
    cudaFuncSetAttribute(node_mma_kernel,
                         cudaFuncAttributeMaxDynamicSharedMemorySize, TILE_SMEM);

    detect_kernel<<<1, 256>>>(eiw);
    zero_hist_kernel<<<(N_NODES + 255) / 256, 256>>>();
    convert_kernel<<<(E_EDGES + 255) / 256, 256>>>(eiw);
    scan_kernel<<<1, 1024>>>();
    permute_kernel<<<(E_EDGES + 255) / 256, 256>>>();
    prep_D_kernel<<<128, 128>>>(Wt, bt, We);
    prep_pack_kernel<<<dim3(36, 5), 256>>>(Wq, Wk, Wv, Ws, We);
    node_mma_kernel<<<dim3((N_NODES + 127) / 128, 4), 256, TILE_SMEM>>>(
        x, bq, bk, bv, bs, out);
    edge_mma_kernel<<<E_EDGES / 256, 256, TILE_SMEM>>>(msg, t, lu);
    agg_kernel<<<(N_NODES * 32 + 255) / 256, 256>>>(out);
}

// round 8
// speedup vs baseline: 3.4887x; 1.1357x over previous
#include <cuda_runtime.h>
#include <cuda_fp16.h>
#include <cstdint>

#define N_NODES 50000
#define E_EDGES 800000
#define BSTRIDE 72          // 32-bit words per packed row (64 half2 + 8 pad)
#define SCAN_BLOCKS 196     // 196*256 = 50176 >= 50000

// ---------------- device scratch ----------------
__device__ int      g_is64;
__device__ int      g_src[E_EDGES];
__device__ int      g_dst[E_EDGES];
__device__ int      g_hist[N_NODES];
__device__ int      g_bsum[SCAN_BLOCKS];
__device__ int      g_boff[SCAN_BLOCKS];
__device__ int      g_off[N_NODES + 1];
__device__ int      g_cur[N_NODES];
__device__ int      g_pos[E_EDGES];               // CSR position of edge e
__device__ float    g_Q[(size_t)N_NODES * 128];
__device__ float    g_K[(size_t)N_NODES * 128];
__device__ uint32_t g_Vh[(size_t)N_NODES * 64];   // V as half2
__device__ uint32_t g_e[(size_t)E_EDGES * 64];    // v[src]+e as half2, CSR order
__device__ float    g_p[(size_t)E_EDGES * 2];     // alpha, CSR order
__device__ float    g_D[7 * 128];                 // time-poly coefficients
__device__ uint32_t g_Bpack[5 * 128 * BSTRIDE];   // packed fp16 weights

// ---------------- helpers ----------------
__device__ __forceinline__ uint32_t h2(float a, float b) {
    uint32_t r;
    asm("cvt.rn.f16x2.f32 %0, %2, %1;" : "=r"(r) : "f"(a), "f"(b));
    return r;
}
__device__ __forceinline__ float2 uh2f(uint32_t u) {
    return __half22float2(*(__half2*)&u);
}
__device__ __forceinline__ uint32_t uhadd2(uint32_t a, uint32_t b) {
    __half2 r = __hadd2(*(__half2*)&a, *(__half2*)&b);
    return *(uint32_t*)&r;
}
__device__ __forceinline__ void mma_f16(float* c, const uint32_t* a, const uint32_t* b) {
    asm volatile(
        "mma.sync.aligned.m16n8k16.row.col.f32.f16.f16.f32 "
        "{%0,%1,%2,%3}, {%4,%5,%6,%7}, {%8,%9}, {%0,%1,%2,%3};"
        : "+f"(c[0]), "+f"(c[1]), "+f"(c[2]), "+f"(c[3])
        : "r"(a[0]), "r"(a[1]), "r"(a[2]), "r"(a[3]), "r"(b[0]), "r"(b[1]));
}

// ---------------- edge index handling + CSR build ----------------
__global__ void detect_kernel(const int* __restrict__ w) {
    __shared__ int any_nz;
    if (threadIdx.x == 0) any_nz = 0;
    __syncthreads();
    int v = 0;
    for (int i = threadIdx.x; i < 2048; i += blockDim.x) v |= w[2 * i + 1];
    if (v) atomicOr(&any_nz, 1);
    __syncthreads();
    if (threadIdx.x == 0) g_is64 = any_nz ? 0 : 1;
}

__global__ void zero_hist_kernel() {
    int i = blockIdx.x * blockDim.x + threadIdx.x;
    if (i < N_NODES) g_hist[i] = 0;
}

__global__ void convert_kernel(const int* __restrict__ w) {
    int e = blockIdx.x * blockDim.x + threadIdx.x;
    if (e >= E_EDGES) return;
    int s, d;
    if (g_is64) { s = w[2 * e]; d = w[2 * (E_EDGES + e)]; }
    else        { s = w[e];     d = w[E_EDGES + e]; }
    g_src[e] = s;
    g_dst[e] = d;
    atomicAdd(&g_hist[d], 1);
}

// hierarchical scan: A) per-block sums  B) scan of sums  C) block-local scan
__global__ void scan_a_kernel() {
    __shared__ int sh[256];
    int idx = blockIdx.x * 256 + threadIdx.x;
    int v = (idx < N_NODES) ? g_hist[idx] : 0;
    sh[threadIdx.x] = v;
    __syncthreads();
    for (int off = 128; off; off >>= 1) {
        if (threadIdx.x < off) sh[threadIdx.x] += sh[threadIdx.x + off];
        __syncthreads();
    }
    if (threadIdx.x == 0) g_bsum[blockIdx.x] = sh[0];
}

__global__ void scan_b_kernel() {   // 1 block, 256 threads
    __shared__ int sh[256];
    int tid = threadIdx.x;
    int v = (tid < SCAN_BLOCKS) ? g_bsum[tid] : 0;
    sh[tid] = v;
    __syncthreads();
    for (int off = 1; off < 256; off <<= 1) {
        int t = (tid >= off) ? sh[tid - off] : 0;
        __syncthreads();
        sh[tid] += t;
        __syncthreads();
    }
    if (tid < SCAN_BLOCKS) g_boff[tid] = sh[tid] - v;
    if (tid == 0) g_off[N_NODES] = E_EDGES;
}

__global__ void scan_c_kernel() {
    __shared__ int sh[256];
    int idx = blockIdx.x * 256 + threadIdx.x;
    int tid = threadIdx.x;
    int v = (idx < N_NODES) ? g_hist[idx] : 0;
    sh[tid] = v;
    __syncthreads();
    for (int off = 1; off < 256; off <<= 1) {
        int t = (tid >= off) ? sh[tid - off] : 0;
        __syncthreads();
        sh[tid] += t;
        __syncthreads();
    }
    if (idx < N_NODES) {
        int excl = sh[tid] - v + g_boff[blockIdx.x];
        g_off[idx] = excl;
        g_cur[idx] = excl;
    }
}

__global__ void permute_kernel() {
    int e = blockIdx.x * blockDim.x + threadIdx.x;
    if (e >= E_EDGES) return;
    g_pos[e] = atomicAdd(&g_cur[g_dst[e]], 1);
}

// ---------------- time-poly coefficients ----------------
__global__ void prep_D_kernel(const float* __restrict__ Wt,
                              const float* __restrict__ bt,
                              const float* __restrict__ We) {
    __shared__ float sh[128];
    int n = blockIdx.x, k = threadIdx.x;
    float w = Wt[k], b = bt[k];
    float we = We[(size_t)k * 128 + n];
    float cb = cosf(b) * we, sb = sinf(b) * we;
    float base[4] = {cb, -sb, -cb, sb};
    float wj = 1.0f;
    for (int j = 0; j < 7; j++) {
        sh[k] = wj * base[j & 3];
        __syncthreads();
        for (int off = 64; off; off >>= 1) {
            if (k < off) sh[k] += sh[k + off];
            __syncthreads();
        }
        if (k == 0) g_D[j * 128 + n] = sh[0];
        __syncthreads();
        wj *= w / (float)(j + 1);
    }
}

// ---------------- pack weights into paired-k fp16 layout ----------------
__global__ void prep_pack_kernel(
    const float* __restrict__ Wq, const float* __restrict__ Wk,
    const float* __restrict__ Wv, const float* __restrict__ Ws,
    const float* __restrict__ We)
{
    int mat = blockIdx.y;
    const float* W;
    int rowbase = 0;
    switch (mat) {
        case 0: W = Wq; break;
        case 1: W = Wk; break;
        case 2: W = Wv; break;
        case 3: W = Ws; break;
        default: W = We; rowbase = 128; break;
    }
    int idx = blockIdx.x * 256 + threadIdx.x;
    if (idx >= 128 * BSTRIDE) return;
    int n = idx / BSTRIDE, s = idx % BSTRIDE;
    uint32_t val = 0;
    if (s < 64) {
        int kp = ((s >> 3) << 3) + ((s & 1) << 2) + ((s & 7) >> 1);
        float v0 = W[(size_t)(rowbase + 2 * kp) * 128 + n];
        float v1 = W[(size_t)(rowbase + 2 * kp + 1) * 128 + n];
        val = h2(v0, v1);
    }
    g_Bpack[(size_t)mat * 128 * BSTRIDE + idx] = val;
}

// ---------------- fp16 node GEMM: [N,128]@[128,128] + bias, x4 ----------------
#define TILE_SMEM (2 * 128 * BSTRIDE * 4)

__global__ __launch_bounds__(256, 2) void node_mma_kernel(
    const float* __restrict__ x,
    const float* __restrict__ bq, const float* __restrict__ bk,
    const float* __restrict__ bv, const float* __restrict__ bs,
    float* __restrict__ out)
{
    extern __shared__ uint32_t smu[];
    uint32_t* Aw = smu;
    uint32_t* Bw = smu + 128 * BSTRIDE;
    __shared__ float bias_s[128];

    const float* b; float* dstp;
    switch (blockIdx.y) {
        case 0: b = bq; dstp = g_Q; break;
        case 1: b = bk; dstp = g_K; break;
        case 2: b = bv; dstp = nullptr; break;  // -> g_Vh fp16
        default: b = bs; dstp = out; break;
    }

    const int tid = threadIdx.x;
    const int wid = tid >> 5, lane = tid & 31;
    const int l4 = lane & 3, lg = lane >> 2;
    const int mB = blockIdx.x * 128;
    const int m0 = (wid & 3) * 32;
    const int n0 = (wid >> 2) * 64;

    if (tid < 128) bias_s[tid] = b[tid];

#pragma unroll
    for (int g = 0; g < 16; g++) {
        int idx = g * 256 + tid;
        int m = idx >> 5, c8 = idx & 31;
        int row = mB + m;
        float4 v = make_float4(0, 0, 0, 0);
        if (row < N_NODES) v = *(const float4*)&x[(size_t)row * 128 + c8 * 4];
        int p0 = ((c8 >> 2) << 3) + ((c8 & 1) << 2) + ((c8 >> 1) & 1);
        Aw[m * BSTRIDE + p0]     = h2(v.x, v.y);
        Aw[m * BSTRIDE + p0 + 2] = h2(v.z, v.w);
    }
    {
        const uint4* src = (const uint4*)&g_Bpack[(size_t)blockIdx.y * 128 * BSTRIDE];
        uint4* dst = (uint4*)Bw;
#pragma unroll
        for (int g = 0; g < 9; g++) dst[g * 256 + tid] = src[g * 256 + tid];
    }
    __syncthreads();

    float acc[2][8][4];
#pragma unroll
    for (int mt = 0; mt < 2; mt++)
#pragma unroll
        for (int nt = 0; nt < 8; nt++)
#pragma unroll
            for (int j = 0; j < 4; j++) acc[mt][nt][j] = 0.0f;

#pragma unroll
    for (int ks = 0; ks < 8; ks++) {
        const int ko = ks * 8 + 2 * l4;
        uint2 av[2][2], bv2[8];
#pragma unroll
        for (int mt = 0; mt < 2; mt++) {
            av[mt][0] = *(const uint2*)&Aw[(m0 + mt * 16 + lg) * BSTRIDE + ko];
            av[mt][1] = *(const uint2*)&Aw[(m0 + mt * 16 + lg + 8) * BSTRIDE + ko];
        }
#pragma unroll
        for (int nt = 0; nt < 8; nt++)
            bv2[nt] = *(const uint2*)&Bw[(n0 + nt * 8 + lg) * BSTRIDE + ko];
#pragma unroll
        for (int mt = 0; mt < 2; mt++) {
            uint32_t a[4] = {av[mt][0].x, av[mt][1].x, av[mt][0].y, av[mt][1].y};
#pragma unroll
            for (int nt = 0; nt < 8; nt++)
                mma_f16(acc[mt][nt], a, (const uint32_t*)&bv2[nt]);
        }
    }

#pragma unroll
    for (int nt = 0; nt < 8; nt++) {
        int cc = n0 + nt * 8 + 2 * l4;
        float b0 = bias_s[cc], b1 = bias_s[cc + 1];
#pragma unroll
        for (int q = 0; q < 4; q++) {
            int row = mB + m0 + (q >> 1) * 16 + (q & 1) * 8 + lg;
            if (row >= N_NODES) continue;
            int mt = q >> 1, pr = (q & 1) * 2;
            float o0 = acc[mt][nt][pr] + b0, o1 = acc[mt][nt][pr + 1] + b1;
            if (blockIdx.y == 2)
                g_Vh[(size_t)row * 64 + (cc >> 1)] = h2(o0, o1);
            else
                *(float2*)&dstp[(size_t)row * 128 + cc] = make_float2(o0, o1);
        }
    }
}

// ---------------- fp16 edge GEMM (256 edges/CTA) + time-poly + alpha ----------------
__global__ __launch_bounds__(256, 2) void edge_mma_kernel(
    const float* __restrict__ msg, const float* __restrict__ t,
    const float* __restrict__ lu)
{
    extern __shared__ uint32_t smu[];
    uint32_t* Bw = smu;                       // persists both halves
    uint32_t* Aw = smu + 128 * BSTRIDE;       // overwritten by Es after mma
    uint32_t* Esh = Aw;                       // [128][68] half2, stride 68

    __shared__ float rel_s[256];
    __shared__ float Ds[7][128];
    __shared__ int srcs[256], dsts[256], poss[256];

    const int tid = threadIdx.x;
    const int wid = tid >> 5, lane = tid & 31;
    const int l4 = lane & 3, lg = lane >> 2;
    const int e0 = blockIdx.x * 256;
    const int m0 = (wid & 3) * 32;
    const int n0 = (wid >> 2) * 64;

    {
        int s = g_src[e0 + tid], d = g_dst[e0 + tid];
        srcs[tid] = s; dsts[tid] = d;
        poss[tid] = g_pos[e0 + tid];
        rel_s[tid] = lu[s] - t[e0 + tid];
        if (tid < 128) {
#pragma unroll
            for (int j = 0; j < 7; j++) Ds[j][tid] = g_D[j * 128 + tid];
        }
    }
    // B fill once
    {
        const uint4* src = (const uint4*)&g_Bpack[(size_t)4 * 128 * BSTRIDE];
        uint4* dst = (uint4*)Bw;
#pragma unroll
        for (int g = 0; g < 9; g++) dst[g * 256 + tid] = src[g * 256 + tid];
    }

    for (int half = 0; half < 2; half++) {
        const int eh = e0 + half * 128;
        __syncthreads();   // prior epilogue Es reads done / B+indices ready
        // A fill
#pragma unroll
        for (int g = 0; g < 16; g++) {
            int idx = g * 256 + tid;
            int m = idx >> 5, c8 = idx & 31;
            float4 v = *(const float4*)&msg[(size_t)(eh + m) * 128 + c8 * 4];
            int p0 = ((c8 >> 2) << 3) + ((c8 & 1) << 2) + ((c8 >> 1) & 1);
            Aw[m * BSTRIDE + p0]     = h2(v.x, v.y);
            Aw[m * BSTRIDE + p0 + 2] = h2(v.z, v.w);
        }
        __syncthreads();

        float acc[2][8][4];
#pragma unroll
        for (int mt = 0; mt < 2; mt++)
#pragma unroll
            for (int nt = 0; nt < 8; nt++)
#pragma unroll
                for (int j = 0; j < 4; j++) acc[mt][nt][j] = 0.0f;

#pragma unroll
        for (int ks = 0; ks < 8; ks++) {
            const int ko = ks * 8 + 2 * l4;
            uint2 av[2][2], bv2[8];
#pragma unroll
            for (int mt = 0; mt < 2; mt++) {
                av[mt][0] = *(const uint2*)&Aw[(m0 + mt * 16 + lg) * BSTRIDE + ko];
                av[mt][1] = *(const uint2*)&Aw[(m0 + mt * 16 + lg + 8) * BSTRIDE + ko];
            }
#pragma unroll
            for (int nt = 0; nt < 8; nt++)
                bv2[nt] = *(const uint2*)&Bw[(n0 + nt * 8 + lg) * BSTRIDE + ko];
#pragma unroll
            for (int mt = 0; mt < 2; mt++) {
                uint32_t a[4] = {av[mt][0].x, av[mt][1].x, av[mt][0].y, av[mt][1].y};
#pragma unroll
                for (int nt = 0; nt < 8; nt++)
                    mma_f16(acc[mt][nt], a, (const uint32_t*)&bv2[nt]);
            }
        }
        __syncthreads();  // all Aw reads done before Es overwrite

        // dump acc + time-poly -> Esh (fp16)
        float relv[4];
        relv[0] = rel_s[half * 128 + m0 + lg];
        relv[1] = rel_s[half * 128 + m0 + lg + 8];
        relv[2] = rel_s[half * 128 + m0 + 16 + lg];
        relv[3] = rel_s[half * 128 + m0 + 16 + lg + 8];
#pragma unroll
        for (int nt = 0; nt < 8; nt++) {
            int cc = n0 + nt * 8 + 2 * l4;
            float C0[7], C1[7];
#pragma unroll
            for (int j = 0; j < 7; j++) { C0[j] = Ds[j][cc]; C1[j] = Ds[j][cc + 1]; }
#pragma unroll
            for (int q = 0; q < 4; q++) {
                float r = relv[q];
                float p0 = C0[6], p1 = C1[6];
#pragma unroll
                for (int j = 5; j >= 0; j--) {
                    p0 = fmaf(p0, r, C0[j]);
                    p1 = fmaf(p1, r, C1[j]);
                }
                int row = m0 + (q >> 1) * 16 + (q & 1) * 8 + lg;
                int mt = q >> 1, pr = (q & 1) * 2;
                Esh[row * 68 + (cc >> 1)] =
                    h2(acc[mt][nt][pr] + p0, acc[mt][nt][pr + 1] + p1);
            }
        }
        __syncthreads();

        // epilogue: thread -> (edge r, head h); outputs written at CSR position
        const int r = tid >> 1, h = tid & 1;
        const int li = half * 128 + r;
        int snode = srcs[li], dnode = dsts[li], pos = poss[li];
        const float4* q4 = (const float4*)&g_Q[(size_t)dnode * 128 + h * 64];
        const float4* k4 = (const float4*)&g_K[(size_t)snode * 128 + h * 64];
        const uint4* v4 = (const uint4*)&g_Vh[(size_t)snode * 64 + h * 32];
        uint4* ge = (uint4*)&g_e[(size_t)pos * 64 + h * 32];
        const uint32_t* es = &Esh[r * 68 + h * 32];
        float s = 0.0f;
#pragma unroll
        for (int c = 0; c < 8; c++) {
            float4 q0 = q4[2 * c], q1 = q4[2 * c + 1];
            float4 k0 = k4[2 * c], k1 = k4[2 * c + 1];
            uint4 vv = v4[c];
            uint4 ee = *(const uint4*)&es[c * 4];
            float2 e0f = uh2f(ee.x), e1f = uh2f(ee.y), e2f = uh2f(ee.z), e3f = uh2f(ee.w);
            s += q0.x * (k0.x + e0f.x) + q0.y * (k0.y + e0f.y) +
                 q0.z * (k0.z + e1f.x) + q0.w * (k0.w + e1f.y) +
                 q1.x * (k1.x + e2f.x) + q1.y * (k1.y + e2f.y) +
                 q1.z * (k1.z + e3f.x) + q1.w * (k1.w + e3f.y);
            uint4 veu;
            veu.x = uhadd2(vv.x, ee.x);
            veu.y = uhadd2(vv.y, ee.y);
            veu.z = uhadd2(vv.z, ee.z);
            veu.w = uhadd2(vv.w, ee.w);
            ge[c] = veu;
        }
        g_p[(size_t)pos * 2 + h] = s * 0.125f;
    }
}

// ---------------- aggregation: warp/node, single-pass online softmax ----------------
__global__ __launch_bounds__(256) void agg_kernel(float* __restrict__ out) {
    int node = (blockIdx.x * blockDim.x + threadIdx.x) >> 5;
    int lane = threadIdx.x & 31;
    if (node >= N_NODES) return;
    int beg = g_off[node], end = g_off[node + 1];
    if (beg == end) return;
    int h = lane >> 4;

    float m = -1e30f, den = 0.0f;
    float a0 = 0, a1 = 0, a2 = 0, a3 = 0;
    for (int i = beg; i < end; i++) {
        float alpha = g_p[(size_t)i * 2 + h];   // warp broadcast (2 values)
        float mn = fmaxf(m, alpha);
        float scale = __expf(m - mn);
        float p = __expf(alpha - mn);
        den = den * scale + p;
        uint2 u = *(const uint2*)&g_e[(size_t)i * 64 + lane * 2];
        float2 p0 = uh2f(u.x), p1 = uh2f(u.y);
        a0 = fmaf(a0, scale, p * p0.x);
        a1 = fmaf(a1, scale, p * p0.y);
        a2 = fmaf(a2, scale, p * p1.x);
        a3 = fmaf(a3, scale, p * p1.y);
        m = mn;
    }
    float rden = 1.0f / den;
    float4* orow = (float4*)&out[(size_t)node * 128 + lane * 4];
    float4 o = *orow;
    o.x = fmaf(a0, rden, o.x);
    o.y = fmaf(a1, rden, o.y);
    o.z = fmaf(a2, rden, o.z);
    o.w = fmaf(a3, rden, o.w);
    *orow = o;
}

// ---------------- launcher ----------------
extern "C" void kernel_launch(void* const* d_in, const int* in_sizes, int n_in,
                              void* d_out, int out_size) {
    const float* x   = (const float*)d_in[0];
    const float* lu  = (const float*)d_in[1];
    const float* t   = (const float*)d_in[2];
    const float* msg = (const float*)d_in[3];
    const int*   eiw = (const int*)d_in[4];
    const float* Wt  = (const float*)d_in[5];
    const float* bt  = (const float*)d_in[6];
    const float* Wq  = (const float*)d_in[7];
    const float* bq  = (const float*)d_in[8];
    const float* Wk  = (const float*)d_in[9];
    const float* bk  = (const float*)d_in[10];
    const float* Wv  = (const float*)d_in[11];
    const float* bv  = (const float*)d_in[12];
    const float* We  = (const float*)d_in[13];
    const float* Ws  = (const float*)d_in[14];
    const float* bs  = (const float*)d_in[15];
    float* out = (float*)d_out;

    cudaFuncSetAttribute(edge_mma_kernel,
                         cudaFuncAttributeMaxDynamicSharedMemorySize, TILE_SMEM);
    cudaFuncSetAttribute(node_mma_kernel,
                         cudaFuncAttributeMaxDynamicSharedMemorySize, TILE_SMEM);

    detect_kernel<<<1, 256>>>(eiw);
    zero_hist_kernel<<<(N_NODES + 255) / 256, 256>>>();
    convert_kernel<<<(E_EDGES + 255) / 256, 256>>>(eiw);
    scan_a_kernel<<<SCAN_BLOCKS, 256>>>();
    scan_b_kernel<<<1, 256>>>();
    scan_c_kernel<<<SCAN_BLOCKS, 256>>>();
    permute_kernel<<<(E_EDGES + 255) / 256, 256>>>();
    prep_D_kernel<<<128, 128>>>(Wt, bt, We);
    prep_pack_kernel<<<dim3(36, 5), 256>>>(Wq, Wk, Wv, Ws, We);
    node_mma_kernel<<<dim3((N_NODES + 127) / 128, 4), 256, TILE_SMEM>>>(
        x, bq, bk, bv, bs, out);
    edge_mma_kernel<<<E_EDGES / 256, 256, TILE_SMEM>>>(msg, t, lu);
    agg_kernel<<<(N_NODES * 32 + 255) / 256, 256>>>(out);
}